// round 1
// baseline (speedup 1.0000x reference)
#include <cuda_runtime.h>
#include <math.h>

#define NN 50000
#define KK 16
#define EE 800000
#define BBATCH 1024
#define MAXM 48
#define FD 9
#define AD 10
#define HH 64
#define NEGINF (-1e9f)

// ---------------- scratch (__device__ globals; no allocation allowed) ----------
__device__ float d_hp0[(NN + 1) * HH];   // [N+1,64] embedded nodes (row 0 = pad)
__device__ float d_hp1[(NN + 1) * HH];   // after iter 1
__device__ float d_hp2[(NN + 1) * HH];   // after iter 2
__device__ float d_gp0[NN + 1];          // hp0 . p
__device__ float d_gp1[NN + 1];          // hp1 . p
__device__ float d_gm1[NN + 1];          // hp1 . q
__device__ float d_elog[EE];             // per-edge logit contribution (iter 1)
__device__ float d_p[HH];                // W_gat @ a[:H]
__device__ float d_q[HH];                // Wm_gat @ a[H:]
__device__ float d_qd[AD];               // W_dist @ q
__device__ float d_c;                    // b_dist . q
__device__ float d_M1[AD * HH];          // W_dist @ Wm_gat
__device__ float d_bm[HH];               // b_dist @ Wm_gat

// ---------------- small constants -------------------------------------------
__global__ void k_consts(const float* __restrict__ Wg, const float* __restrict__ Wm,
                         const float* __restrict__ a,  const float* __restrict__ Wd,
                         const float* __restrict__ bd) {
    int j = threadIdx.x;  // 0..63
    float p = 0.f, q = 0.f;
    #pragma unroll 8
    for (int t = 0; t < HH; t++) {
        p += Wg[j * HH + t] * a[t];
        q += Wm[j * HH + t] * a[HH + t];
    }
    d_p[j] = p;
    d_q[j] = q;
    __shared__ float sq[HH];
    sq[j] = q;
    __syncthreads();
    if (j < AD) {
        float s = 0.f;
        for (int t = 0; t < HH; t++) s += Wd[j * HH + t] * sq[t];
        d_qd[j] = s;
    }
    if (j == 0) {
        float s = 0.f;
        for (int t = 0; t < HH; t++) s += bd[t] * sq[t];
        d_c = s;
    }
    for (int r = 0; r < AD; r++) {
        float s = 0.f;
        for (int i = 0; i < HH; i++) s += Wd[r * HH + i] * Wm[i * HH + j];
        d_M1[r * HH + j] = s;
    }
    float s = 0.f;
    for (int i = 0; i < HH; i++) s += bd[i] * Wm[i * HH + j];
    d_bm[j] = s;
}

// ---------------- node embedding + gp0 --------------------------------------
__global__ void k_embed(const float* __restrict__ tf, const float* __restrict__ We,
                        const float* __restrict__ be) {
    int gw = (blockIdx.x * blockDim.x + threadIdx.x) >> 5;
    int lane = threadIdx.x & 31;
    if (gw > NN) return;
    float2* hpv = (float2*)d_hp0;
    if (gw == 0) {
        hpv[lane] = make_float2(0.f, 0.f);
        if (lane == 0) d_gp0[0] = 0.f;
        return;
    }
    int n = gw - 1;
    const float* r = tf + n * FD;
    float2 acc = make_float2(be[2 * lane], be[2 * lane + 1]);
    #pragma unroll
    for (int t = 0; t < FD; t++) {
        float x = __ldg(r + t);
        acc.x += x * We[t * HH + 2 * lane];
        acc.y += x * We[t * HH + 2 * lane + 1];
    }
    hpv[gw * 32 + lane] = acc;
    float part = acc.x * d_p[2 * lane] + acc.y * d_p[2 * lane + 1];
    #pragma unroll
    for (int m = 16; m; m >>= 1) part += __shfl_xor_sync(0xffffffffu, part, m);
    if (lane == 0) d_gp0[gw] = part;
}

// ---------------- per-edge logit scalar (iter 1) -----------------------------
__global__ void k_elog(const float* __restrict__ fdg, const float* __restrict__ rij) {
    int e = blockIdx.x * blockDim.x + threadIdx.x;
    if (e >= EE) return;
    float s = d_c + rij[e] * d_qd[9];
    const float* x = fdg + (long)e * FD;
    #pragma unroll
    for (int r = 0; r < FD; r++) s += x[r] * d_qd[r];
    d_elog[e] = s;
}

// ---------------- iteration 1 ------------------------------------------------
__global__ __launch_bounds__(256) void k_iter1(const int* __restrict__ se,
                                               const int* __restrict__ bs,
                                               const float* __restrict__ fdg,
                                               const float* __restrict__ rij,
                                               const float* __restrict__ Wg) {
    __shared__ float2 sWg[HH * 32];
    __shared__ float2 sM1[AD * 32];
    for (int i = threadIdx.x; i < HH * 32; i += blockDim.x) sWg[i] = ((const float2*)Wg)[i];
    for (int i = threadIdx.x; i < AD * 32; i += blockDim.x) sM1[i] = ((const float2*)d_M1)[i];
    __syncthreads();

    int gw = (blockIdx.x * blockDim.x + threadIdx.x) >> 5;
    int lane = threadIdx.x & 31;
    if (gw > NN) return;
    float2* hp1v = (float2*)d_hp1;
    if (gw == 0) {
        hp1v[lane] = make_float2(0.f, 0.f);
        if (lane == 0) { d_gp1[0] = 0.f; d_gm1[0] = 0.f; }
        return;
    }
    int n = gw - 1;

    int idx = 0, e = 0;
    float logit = NEGINF;
    if (lane < KK) {
        idx = se[n * KK + lane];
        e   = bs[n * KK + lane];
        float v = d_gp0[idx] + d_elog[e];
        v = (v > 0.f) ? v : 0.2f * v;
        logit = (idx == 0) ? NEGINF : v;
    }
    // softmax over 16 lanes (width-16 segment)
    float mx = logit;
    #pragma unroll
    for (int m = 8; m; m >>= 1) mx = fmaxf(mx, __shfl_xor_sync(0xffffffffu, mx, m, 16));
    float ex = __expf(logit - mx);
    float sum = ex;
    #pragma unroll
    for (int m = 8; m; m >>= 1) sum += __shfl_xor_sync(0xffffffffu, sum, m, 16);
    float alpha = ex / sum;

    float2 accA = make_float2(0.f, 0.f);
    float accX = 0.f;
    const float2* hpv = (const float2*)d_hp0;
    #pragma unroll
    for (int k = 0; k < KK; k++) {
        float a = __shfl_sync(0xffffffffu, alpha, k);
        int   i = __shfl_sync(0xffffffffu, idx, k);
        int  ee = __shfl_sync(0xffffffffu, e, k);
        float2 v = hpv[i * 32 + lane];
        accA.x += a * v.x;
        accA.y += a * v.y;
        if (lane < AD) {
            float x = (lane < FD) ? fdg[(long)ee * FD + lane] : rij[ee];
            accX += a * x;
        }
    }

    float o0 = d_bm[2 * lane], o1 = d_bm[2 * lane + 1];
    #pragma unroll
    for (int s = 0; s < 32; s++) {
        float ax = __shfl_sync(0xffffffffu, accA.x, s);
        float ay = __shfl_sync(0xffffffffu, accA.y, s);
        float2 w0 = sWg[(2 * s) * 32 + lane];
        float2 w1 = sWg[(2 * s + 1) * 32 + lane];
        o0 += ax * w0.x + ay * w1.x;
        o1 += ax * w0.y + ay * w1.y;
    }
    #pragma unroll
    for (int r = 0; r < AD; r++) {
        float xr = __shfl_sync(0xffffffffu, accX, r);
        float2 m = sM1[r * 32 + lane];
        o0 += xr * m.x;
        o1 += xr * m.y;
    }
    o0 = (o0 > 0.f) ? o0 : expm1f(o0);
    o1 = (o1 > 0.f) ? o1 : expm1f(o1);
    hp1v[gw * 32 + lane] = make_float2(o0, o1);

    float pp = o0 * d_p[2 * lane] + o1 * d_p[2 * lane + 1];
    float qq = o0 * d_q[2 * lane] + o1 * d_q[2 * lane + 1];
    #pragma unroll
    for (int m = 16; m; m >>= 1) {
        pp += __shfl_xor_sync(0xffffffffu, pp, m);
        qq += __shfl_xor_sync(0xffffffffu, qq, m);
    }
    if (lane == 0) { d_gp1[gw] = pp; d_gm1[gw] = qq; }
}

// ---------------- iteration 2 ------------------------------------------------
__global__ __launch_bounds__(256) void k_iter2(const int* __restrict__ se,
                                               const int* __restrict__ bs,
                                               const int* __restrict__ su,
                                               const int* __restrict__ sul,
                                               const float* __restrict__ Wg,
                                               const float* __restrict__ Wm) {
    __shared__ float2 sWg[HH * 32];
    __shared__ float2 sWm[HH * 32];
    for (int i = threadIdx.x; i < HH * 32; i += blockDim.x) {
        sWg[i] = ((const float2*)Wg)[i];
        sWm[i] = ((const float2*)Wm)[i];
    }
    __syncthreads();

    int gw = (blockIdx.x * blockDim.x + threadIdx.x) >> 5;
    int lane = threadIdx.x & 31;
    if (gw > NN) return;
    float2* hp2v = (float2*)d_hp2;
    if (gw == 0) {
        hp2v[lane] = make_float2(0.f, 0.f);
        return;
    }
    int n = gw - 1;

    int idx = 0, j = 0;
    float msk = 0.f;
    float logit = NEGINF;
    if (lane < KK) {
        idx = se[n * KK + lane];
        int e = bs[n * KK + lane];
        j = su[e];
        msk = (sul[e] > 0) ? 1.f : 0.f;
        float v = d_gp1[idx] + msk * d_gm1[j];
        v = (v > 0.f) ? v : 0.2f * v;
        logit = (idx == 0) ? NEGINF : v;
    }
    float mx = logit;
    #pragma unroll
    for (int m = 8; m; m >>= 1) mx = fmaxf(mx, __shfl_xor_sync(0xffffffffu, mx, m, 16));
    float ex = __expf(logit - mx);
    float sum = ex;
    #pragma unroll
    for (int m = 8; m; m >>= 1) sum += __shfl_xor_sync(0xffffffffu, sum, m, 16);
    float alpha = ex / sum;

    float2 accA = make_float2(0.f, 0.f);
    float2 accB = make_float2(0.f, 0.f);
    const float2* hv = (const float2*)d_hp1;
    #pragma unroll
    for (int k = 0; k < KK; k++) {
        float a  = __shfl_sync(0xffffffffu, alpha, k);
        int   i  = __shfl_sync(0xffffffffu, idx, k);
        int   jj = __shfl_sync(0xffffffffu, j, k);
        float mm = __shfl_sync(0xffffffffu, msk, k);
        float2 v = hv[i * 32 + lane];
        accA.x += a * v.x;
        accA.y += a * v.y;
        float am = a * mm;
        float2 u = hv[jj * 32 + lane];
        accB.x += am * u.x;
        accB.y += am * u.y;
    }

    float o0 = 0.f, o1 = 0.f;
    #pragma unroll
    for (int s = 0; s < 32; s++) {
        float ax = __shfl_sync(0xffffffffu, accA.x, s);
        float ay = __shfl_sync(0xffffffffu, accA.y, s);
        float bx = __shfl_sync(0xffffffffu, accB.x, s);
        float by = __shfl_sync(0xffffffffu, accB.y, s);
        float2 w0 = sWg[(2 * s) * 32 + lane];
        float2 w1 = sWg[(2 * s + 1) * 32 + lane];
        float2 m0 = sWm[(2 * s) * 32 + lane];
        float2 m1 = sWm[(2 * s + 1) * 32 + lane];
        o0 += ax * w0.x + ay * w1.x + bx * m0.x + by * m1.x;
        o1 += ax * w0.y + ay * w1.y + bx * m0.y + by * m1.y;
    }
    o0 = (o0 > 0.f) ? o0 : expm1f(o0);
    o1 = (o1 > 0.f) ? o1 : expm1f(o1);
    hp2v[gw * 32 + lane] = make_float2(o0, o1);
}

// ---------------- readout ----------------------------------------------------
__global__ void k_out(const int* __restrict__ ls, float* __restrict__ out) {
    int gw = (blockIdx.x * blockDim.x + threadIdx.x) >> 5;
    int lane = threadIdx.x & 31;
    if (gw >= BBATCH) return;
    const float2* hv = (const float2*)d_hp2;
    const int* row = ls + gw * MAXM;
    float2 acc = make_float2(0.f, 0.f);
    #pragma unroll 8
    for (int m = 0; m < MAXM; m++) {
        int i = __ldg(row + m);
        float2 v = hv[i * 32 + lane];
        acc.x += v.x;
        acc.y += v.y;
    }
    ((float2*)out)[gw * 32 + lane] = acc;
}

// ---------------- launch -----------------------------------------------------
extern "C" void kernel_launch(void* const* d_in, const int* in_sizes, int n_in,
                              void* d_out, int out_size) {
    const float* tf  = (const float*)d_in[0];   // target_features [N,9]
    const float* fdg = (const float*)d_in[1];   // feature_dist_graph [E,9]
    const float* rij = (const float*)d_in[2];   // rij_dist_pairs [E]
    const int*   se  = (const int*)d_in[3];     // start_end_env [N,16]
    const int*   bs  = (const int*)d_in[4];     // b_scope [N,16]
    const int*   ls  = (const int*)d_in[5];     // l_scope [B,48]
    const int*   su  = (const int*)d_in[6];     // scope_update [E]
    const int*   sul = (const int*)d_in[7];     // scope_update_lig [E]
    const float* We  = (const float*)d_in[8];   // W_emb [9,64]
    const float* be  = (const float*)d_in[9];   // b_emb [64]
    const float* Wd  = (const float*)d_in[10];  // W_dist [10,64]
    const float* bd  = (const float*)d_in[11];  // b_dist [64]
    const float* Wg  = (const float*)d_in[12];  // W_gat [64,64]
    const float* Wm  = (const float*)d_in[13];  // Wm_gat [64,64]
    const float* ag  = (const float*)d_in[14];  // a_gat [128]

    int node_blocks = (NN + 1 + 7) / 8;  // 8 warps/block, one warp per node (+pad row)

    k_consts<<<1, 64>>>(Wg, Wm, ag, Wd, bd);
    k_embed<<<node_blocks, 256>>>(tf, We, be);
    k_elog<<<(EE + 255) / 256, 256>>>(fdg, rij);
    k_iter1<<<node_blocks, 256>>>(se, bs, fdg, rij, Wg);
    k_iter2<<<node_blocks, 256>>>(se, bs, su, sul, Wg, Wm);
    k_out<<<(BBATCH + 7) / 8, 256>>>(ls, (float*)d_out);
}

// round 2
// speedup vs baseline: 1.9840x; 1.9840x over previous
#include <cuda_runtime.h>
#include <math.h>

#define NN 50000
#define KK 16
#define EE 800000
#define BBATCH 1024
#define MAXM 48
#define FD 9
#define AD 10
#define HH 64
#define NEGINF (-1e9f)

// ---------------- scratch (__device__ globals) --------------------------------
__device__ float4 d_hp0v[(NN + 1) * 16];  // [N+1,64] as float4
__device__ float4 d_hp1v[(NN + 1) * 16];
__device__ float4 d_hp2v[(NN + 1) * 16];
__device__ float d_gp0[NN + 1];
__device__ float d_gp1[NN + 1];
__device__ float d_gm1[NN + 1];
__device__ float d_elog[EE];
__device__ float4 d_p4[16];               // W_gat @ a[:H]
__device__ float4 d_q4[16];               // Wm_gat @ a[H:]
__device__ float d_qd[AD];                // W_dist @ q
__device__ float d_c;                     // b_dist . q
__device__ float4 d_M14[AD * 16];         // W_dist @ Wm_gat
__device__ float4 d_bm4[16];              // b_dist @ Wm_gat

// ---------------- small constants --------------------------------------------
__global__ void k_consts(const float* __restrict__ Wg, const float* __restrict__ Wm,
                         const float* __restrict__ a,  const float* __restrict__ Wd,
                         const float* __restrict__ bd) {
    int j = threadIdx.x;  // 0..63
    float p = 0.f, q = 0.f;
    #pragma unroll 8
    for (int t = 0; t < HH; t++) {
        p += Wg[j * HH + t] * a[t];
        q += Wm[j * HH + t] * a[HH + t];
    }
    ((float*)d_p4)[j] = p;
    ((float*)d_q4)[j] = q;
    __shared__ float sq[HH];
    sq[j] = q;
    __syncthreads();
    if (j < AD) {
        float s = 0.f;
        for (int t = 0; t < HH; t++) s += Wd[j * HH + t] * sq[t];
        d_qd[j] = s;
    }
    if (j == 0) {
        float s = 0.f;
        for (int t = 0; t < HH; t++) s += bd[t] * sq[t];
        d_c = s;
    }
    for (int r = 0; r < AD; r++) {
        float s = 0.f;
        for (int i = 0; i < HH; i++) s += Wd[r * HH + i] * Wm[i * HH + j];
        ((float*)d_M14)[r * HH + j] = s;
    }
    float s = 0.f;
    for (int i = 0; i < HH; i++) s += bd[i] * Wm[i * HH + j];
    ((float*)d_bm4)[j] = s;
}

// ---------------- node embedding + gp0 (2 nodes / warp) -----------------------
__global__ __launch_bounds__(256) void k_embed(const float* __restrict__ tf,
                                               const float* __restrict__ We,
                                               const float* __restrict__ be) {
    int wid = (blockIdx.x * blockDim.x + threadIdx.x) >> 5;
    int l = threadIdx.x & 31;
    int sub = l & 15;
    int row = wid * 2 + (l >> 4);   // 0..NN (row 0 = pad)
    if (row > NN) return;
    float4 acc = make_float4(0.f, 0.f, 0.f, 0.f);
    if (row > 0) {
        int n = row - 1;
        const float* r = tf + n * FD;
        acc = ((const float4*)be)[sub];
        #pragma unroll
        for (int t = 0; t < FD; t++) {
            float x = __ldg(r + t);
            float4 w = ((const float4*)We)[t * 16 + sub];
            acc.x += x * w.x; acc.y += x * w.y; acc.z += x * w.z; acc.w += x * w.w;
        }
    }
    d_hp0v[row * 16 + sub] = acc;
    float4 p = d_p4[sub];
    float pp = acc.x * p.x + acc.y * p.y + acc.z * p.z + acc.w * p.w;
    #pragma unroll
    for (int m = 8; m; m >>= 1) pp += __shfl_xor_sync(0xffffffffu, pp, m, 16);
    if (sub == 0) d_gp0[row] = pp;
}

// ---------------- per-edge logit scalar (iter 1) -------------------------------
__global__ void k_elog(const float* __restrict__ fdg, const float* __restrict__ rij) {
    int e = blockIdx.x * blockDim.x + threadIdx.x;
    if (e >= EE) return;
    float s = d_c + rij[e] * d_qd[9];
    const float* x = fdg + (long)e * FD;
    #pragma unroll
    for (int r = 0; r < FD; r++) s += x[r] * d_qd[r];
    d_elog[e] = s;
}

// ---------------- iteration 1 (2 nodes / warp, float4 lanes) -------------------
__global__ __launch_bounds__(256) void k_iter1(const int* __restrict__ se,
                                               const int* __restrict__ bs,
                                               const float* __restrict__ fdg,
                                               const float* __restrict__ rij,
                                               const float* __restrict__ Wg) {
    __shared__ float4 sW[HH * 16];     // Wg rows as float4
    __shared__ float4 sM[AD * 16];     // M1 rows as float4
    for (int i = threadIdx.x; i < HH * 16; i += blockDim.x) sW[i] = ((const float4*)Wg)[i];
    for (int i = threadIdx.x; i < AD * 16; i += blockDim.x) sM[i] = d_M14[i];
    __syncthreads();

    int wid = (blockIdx.x * blockDim.x + threadIdx.x) >> 5;
    int l = threadIdx.x & 31;
    int base = l & 16;
    int sub = l & 15;
    int row = wid * 2 + (l >> 4);      // this half-warp's node row
    bool live = (row >= 1) && (row <= NN);

    int idx = 0, eix = 0;
    float logit = NEGINF;
    if (live) {
        int n = row - 1;
        idx = se[n * KK + sub];
        eix = bs[n * KK + sub];
        float v = d_gp0[idx] + d_elog[eix];
        v = (v > 0.f) ? v : 0.2f * v;
        logit = (idx == 0) ? NEGINF : v;
    }
    // softmax over the 16 lanes of this half
    float mx = logit;
    #pragma unroll
    for (int m = 8; m; m >>= 1) mx = fmaxf(mx, __shfl_xor_sync(0xffffffffu, mx, m, 16));
    float ex = __expf(logit - mx);
    float sum = ex;
    #pragma unroll
    for (int m = 8; m; m >>= 1) sum += __shfl_xor_sync(0xffffffffu, sum, m, 16);
    float alpha = ex / sum;

    float4 accA = make_float4(0.f, 0.f, 0.f, 0.f);
    float accX = 0.f;
    #pragma unroll
    for (int k = 0; k < KK; k++) {
        float a = __shfl_sync(0xffffffffu, alpha, base + k);
        int   i = __shfl_sync(0xffffffffu, idx,   base + k);
        int   e = __shfl_sync(0xffffffffu, eix,   base + k);
        float4 v = d_hp0v[i * 16 + sub];
        accA.x += a * v.x; accA.y += a * v.y; accA.z += a * v.z; accA.w += a * v.w;
        if (sub < AD) {
            float x = (sub < FD) ? fdg[(long)e * FD + sub] : rij[e];
            accX += a * x;
        }
    }

    float4 o = d_bm4[sub];
    #pragma unroll
    for (int s4 = 0; s4 < 16; s4++) {
        float xs0 = __shfl_sync(0xffffffffu, accA.x, base + s4);
        float xs1 = __shfl_sync(0xffffffffu, accA.y, base + s4);
        float xs2 = __shfl_sync(0xffffffffu, accA.z, base + s4);
        float xs3 = __shfl_sync(0xffffffffu, accA.w, base + s4);
        float4 w0 = sW[(4 * s4 + 0) * 16 + sub];
        float4 w1 = sW[(4 * s4 + 1) * 16 + sub];
        float4 w2 = sW[(4 * s4 + 2) * 16 + sub];
        float4 w3 = sW[(4 * s4 + 3) * 16 + sub];
        o.x += xs0 * w0.x + xs1 * w1.x + xs2 * w2.x + xs3 * w3.x;
        o.y += xs0 * w0.y + xs1 * w1.y + xs2 * w2.y + xs3 * w3.y;
        o.z += xs0 * w0.z + xs1 * w1.z + xs2 * w2.z + xs3 * w3.z;
        o.w += xs0 * w0.w + xs1 * w1.w + xs2 * w2.w + xs3 * w3.w;
    }
    #pragma unroll
    for (int r = 0; r < AD; r++) {
        float xr = __shfl_sync(0xffffffffu, accX, base + r);
        float4 m = sM[r * 16 + sub];
        o.x += xr * m.x; o.y += xr * m.y; o.z += xr * m.z; o.w += xr * m.w;
    }
    o.x = (o.x > 0.f) ? o.x : expm1f(o.x);
    o.y = (o.y > 0.f) ? o.y : expm1f(o.y);
    o.z = (o.z > 0.f) ? o.z : expm1f(o.z);
    o.w = (o.w > 0.f) ? o.w : expm1f(o.w);
    if (!live) o = make_float4(0.f, 0.f, 0.f, 0.f);

    float4 p = d_p4[sub], q = d_q4[sub];
    float pp = o.x * p.x + o.y * p.y + o.z * p.z + o.w * p.w;
    float qq = o.x * q.x + o.y * q.y + o.z * q.z + o.w * q.w;
    #pragma unroll
    for (int m = 8; m; m >>= 1) {
        pp += __shfl_xor_sync(0xffffffffu, pp, m, 16);
        qq += __shfl_xor_sync(0xffffffffu, qq, m, 16);
    }
    if (row <= NN) {
        d_hp1v[row * 16 + sub] = o;
        if (sub == 0) { d_gp1[row] = pp; d_gm1[row] = qq; }
    }
}

// ---------------- iteration 2 (2 nodes / warp, float4 lanes) -------------------
__global__ __launch_bounds__(256) void k_iter2(const int* __restrict__ se,
                                               const int* __restrict__ bs,
                                               const int* __restrict__ su,
                                               const int* __restrict__ sul,
                                               const float* __restrict__ Wg,
                                               const float* __restrict__ Wm) {
    __shared__ float4 sWg[HH * 16];
    __shared__ float4 sWm[HH * 16];
    for (int i = threadIdx.x; i < HH * 16; i += blockDim.x) {
        sWg[i] = ((const float4*)Wg)[i];
        sWm[i] = ((const float4*)Wm)[i];
    }
    __syncthreads();

    int wid = (blockIdx.x * blockDim.x + threadIdx.x) >> 5;
    int l = threadIdx.x & 31;
    int base = l & 16;
    int sub = l & 15;
    int row = wid * 2 + (l >> 4);
    bool live = (row >= 1) && (row <= NN);

    int idx = 0, j = 0;
    float msk = 0.f;
    float logit = NEGINF;
    if (live) {
        int n = row - 1;
        idx = se[n * KK + sub];
        int e = bs[n * KK + sub];
        j = su[e];
        msk = (sul[e] > 0) ? 1.f : 0.f;
        float v = d_gp1[idx] + msk * d_gm1[j];
        v = (v > 0.f) ? v : 0.2f * v;
        logit = (idx == 0) ? NEGINF : v;
    }
    float mx = logit;
    #pragma unroll
    for (int m = 8; m; m >>= 1) mx = fmaxf(mx, __shfl_xor_sync(0xffffffffu, mx, m, 16));
    float ex = __expf(logit - mx);
    float sum = ex;
    #pragma unroll
    for (int m = 8; m; m >>= 1) sum += __shfl_xor_sync(0xffffffffu, sum, m, 16);
    float alpha = ex / sum;

    float4 accA = make_float4(0.f, 0.f, 0.f, 0.f);
    float4 accB = make_float4(0.f, 0.f, 0.f, 0.f);
    #pragma unroll
    for (int k = 0; k < KK; k++) {
        float a  = __shfl_sync(0xffffffffu, alpha, base + k);
        int   i  = __shfl_sync(0xffffffffu, idx,   base + k);
        int   jj = __shfl_sync(0xffffffffu, j,     base + k);
        float mm = __shfl_sync(0xffffffffu, msk,   base + k);
        float4 v = d_hp1v[i * 16 + sub];
        accA.x += a * v.x; accA.y += a * v.y; accA.z += a * v.z; accA.w += a * v.w;
        float am = a * mm;
        float4 u = d_hp1v[jj * 16 + sub];
        accB.x += am * u.x; accB.y += am * u.y; accB.z += am * u.z; accB.w += am * u.w;
    }

    float4 o = make_float4(0.f, 0.f, 0.f, 0.f);
    #pragma unroll
    for (int s4 = 0; s4 < 16; s4++) {
        float a0 = __shfl_sync(0xffffffffu, accA.x, base + s4);
        float a1 = __shfl_sync(0xffffffffu, accA.y, base + s4);
        float a2 = __shfl_sync(0xffffffffu, accA.z, base + s4);
        float a3 = __shfl_sync(0xffffffffu, accA.w, base + s4);
        float b0 = __shfl_sync(0xffffffffu, accB.x, base + s4);
        float b1 = __shfl_sync(0xffffffffu, accB.y, base + s4);
        float b2 = __shfl_sync(0xffffffffu, accB.z, base + s4);
        float b3 = __shfl_sync(0xffffffffu, accB.w, base + s4);
        float4 g0 = sWg[(4 * s4 + 0) * 16 + sub];
        float4 g1 = sWg[(4 * s4 + 1) * 16 + sub];
        float4 g2 = sWg[(4 * s4 + 2) * 16 + sub];
        float4 g3 = sWg[(4 * s4 + 3) * 16 + sub];
        float4 m0 = sWm[(4 * s4 + 0) * 16 + sub];
        float4 m1 = sWm[(4 * s4 + 1) * 16 + sub];
        float4 m2 = sWm[(4 * s4 + 2) * 16 + sub];
        float4 m3 = sWm[(4 * s4 + 3) * 16 + sub];
        o.x += a0 * g0.x + a1 * g1.x + a2 * g2.x + a3 * g3.x
             + b0 * m0.x + b1 * m1.x + b2 * m2.x + b3 * m3.x;
        o.y += a0 * g0.y + a1 * g1.y + a2 * g2.y + a3 * g3.y
             + b0 * m0.y + b1 * m1.y + b2 * m2.y + b3 * m3.y;
        o.z += a0 * g0.z + a1 * g1.z + a2 * g2.z + a3 * g3.z
             + b0 * m0.z + b1 * m1.z + b2 * m2.z + b3 * m3.z;
        o.w += a0 * g0.w + a1 * g1.w + a2 * g2.w + a3 * g3.w
             + b0 * m0.w + b1 * m1.w + b2 * m2.w + b3 * m3.w;
    }
    o.x = (o.x > 0.f) ? o.x : expm1f(o.x);
    o.y = (o.y > 0.f) ? o.y : expm1f(o.y);
    o.z = (o.z > 0.f) ? o.z : expm1f(o.z);
    o.w = (o.w > 0.f) ? o.w : expm1f(o.w);
    if (!live) o = make_float4(0.f, 0.f, 0.f, 0.f);
    if (row <= NN) d_hp2v[row * 16 + sub] = o;
}

// ---------------- readout (2 molecules / warp) ---------------------------------
__global__ __launch_bounds__(256) void k_out(const int* __restrict__ ls,
                                             float* __restrict__ out) {
    int wid = (blockIdx.x * blockDim.x + threadIdx.x) >> 5;
    int l = threadIdx.x & 31;
    int sub = l & 15;
    int mol = wid * 2 + (l >> 4);
    if (mol >= BBATCH) return;
    const int* row = ls + mol * MAXM;
    float4 acc = make_float4(0.f, 0.f, 0.f, 0.f);
    #pragma unroll 8
    for (int m = 0; m < MAXM; m++) {
        int i = __ldg(row + m);
        float4 v = d_hp2v[i * 16 + sub];
        acc.x += v.x; acc.y += v.y; acc.z += v.z; acc.w += v.w;
    }
    ((float4*)out)[mol * 16 + sub] = acc;
}

// ---------------- launch -------------------------------------------------------
extern "C" void kernel_launch(void* const* d_in, const int* in_sizes, int n_in,
                              void* d_out, int out_size) {
    const float* tf  = (const float*)d_in[0];
    const float* fdg = (const float*)d_in[1];
    const float* rij = (const float*)d_in[2];
    const int*   se  = (const int*)d_in[3];
    const int*   bs  = (const int*)d_in[4];
    const int*   ls  = (const int*)d_in[5];
    const int*   su  = (const int*)d_in[6];
    const int*   sul = (const int*)d_in[7];
    const float* We  = (const float*)d_in[8];
    const float* be  = (const float*)d_in[9];
    const float* Wd  = (const float*)d_in[10];
    const float* bd  = (const float*)d_in[11];
    const float* Wg  = (const float*)d_in[12];
    const float* Wm  = (const float*)d_in[13];
    const float* ag  = (const float*)d_in[14];

    int warps = (NN + 1 + 1) / 2;           // 2 rows per warp
    int node_blocks = (warps + 7) / 8;      // 8 warps per block

    k_consts<<<1, 64>>>(Wg, Wm, ag, Wd, bd);
    k_embed<<<node_blocks, 256>>>(tf, We, be);
    k_elog<<<(EE + 255) / 256, 256>>>(fdg, rij);
    k_iter1<<<node_blocks, 256>>>(se, bs, fdg, rij, Wg);
    k_iter2<<<node_blocks, 256>>>(se, bs, su, sul, Wg, Wm);
    k_out<<<(BBATCH / 2 + 7) / 8, 256>>>(ls, (float*)d_out);
}

// round 3
// speedup vs baseline: 2.0400x; 1.0282x over previous
#include <cuda_runtime.h>
#include <math.h>

#define NN 50000
#define KK 16
#define EE 800000
#define BBATCH 1024
#define MAXM 48
#define FD 9
#define AD 10
#define HH 64
#define NEGINF (-1e9f)
#define NPB 64            // nodes per block (iter kernels)
#define RNDS 4            // NPB / 16

// ---------------- scratch ------------------------------------------------------
__device__ float4 d_hp0v[(NN + 1) * 16];
__device__ float4 d_hp1v[(NN + 1) * 16];
__device__ float4 d_hp2v[(NN + 1) * 16];
__device__ float d_gp0[NN + 1];
__device__ float d_gp1[NN + 1];
__device__ float d_gm1[NN + 1];
__device__ float d_elog[EE];
__device__ float4 d_p4[16];
__device__ float4 d_q4[16];
__device__ float d_qd[AD];
__device__ float d_c;
__device__ float4 d_M14[AD * 16];
__device__ float4 d_bm4[16];

// ---------------- small constants ----------------------------------------------
__global__ void k_consts(const float* __restrict__ Wg, const float* __restrict__ Wm,
                         const float* __restrict__ a,  const float* __restrict__ Wd,
                         const float* __restrict__ bd) {
    int j = threadIdx.x;  // 0..63
    float p = 0.f, q = 0.f;
    #pragma unroll 8
    for (int t = 0; t < HH; t++) {
        p += Wg[j * HH + t] * a[t];
        q += Wm[j * HH + t] * a[HH + t];
    }
    ((float*)d_p4)[j] = p;
    ((float*)d_q4)[j] = q;
    __shared__ float sq[HH];
    sq[j] = q;
    __syncthreads();
    if (j < AD) {
        float s = 0.f;
        for (int t = 0; t < HH; t++) s += Wd[j * HH + t] * sq[t];
        d_qd[j] = s;
    }
    if (j == 0) {
        float s = 0.f;
        for (int t = 0; t < HH; t++) s += bd[t] * sq[t];
        d_c = s;
    }
    for (int r = 0; r < AD; r++) {
        float s = 0.f;
        for (int i = 0; i < HH; i++) s += Wd[r * HH + i] * Wm[i * HH + j];
        ((float*)d_M14)[r * HH + j] = s;
    }
    float s = 0.f;
    for (int i = 0; i < HH; i++) s += bd[i] * Wm[i * HH + j];
    ((float*)d_bm4)[j] = s;
}

// ---------------- node embedding + gp0 (2 nodes / warp) -------------------------
__global__ __launch_bounds__(256) void k_embed(const float* __restrict__ tf,
                                               const float* __restrict__ We,
                                               const float* __restrict__ be) {
    int wid = (blockIdx.x * blockDim.x + threadIdx.x) >> 5;
    int l = threadIdx.x & 31;
    int sub = l & 15;
    int row = wid * 2 + (l >> 4);
    if (row > NN) return;
    float4 acc = make_float4(0.f, 0.f, 0.f, 0.f);
    if (row > 0) {
        int n = row - 1;
        const float* r = tf + n * FD;
        acc = ((const float4*)be)[sub];
        #pragma unroll
        for (int t = 0; t < FD; t++) {
            float x = __ldg(r + t);
            float4 w = ((const float4*)We)[t * 16 + sub];
            acc.x += x * w.x; acc.y += x * w.y; acc.z += x * w.z; acc.w += x * w.w;
        }
    }
    d_hp0v[row * 16 + sub] = acc;
    float4 p = d_p4[sub];
    float pp = acc.x * p.x + acc.y * p.y + acc.z * p.z + acc.w * p.w;
    #pragma unroll
    for (int m = 8; m; m >>= 1) pp += __shfl_xor_sync(0xffffffffu, pp, m, 16);
    if (sub == 0) d_gp0[row] = pp;
}

// ---------------- per-edge logit scalar (iter 1) --------------------------------
__global__ void k_elog(const float* __restrict__ fdg, const float* __restrict__ rij) {
    int e = blockIdx.x * blockDim.x + threadIdx.x;
    if (e >= EE) return;
    float s = d_c + rij[e] * d_qd[9];
    const float* x = fdg + (long)e * FD;
    #pragma unroll
    for (int r = 0; r < FD; r++) s += x[r] * d_qd[r];
    d_elog[e] = s;
}

#define FMA4(o, a, w0, w1, w2, w3)                                     \
    o.x += a.x * w0.x + a.y * w1.x + a.z * w2.x + a.w * w3.x;          \
    o.y += a.x * w0.y + a.y * w1.y + a.z * w2.y + a.w * w3.y;          \
    o.z += a.x * w0.z + a.y * w1.z + a.z * w2.z + a.w * w3.z;          \
    o.w += a.x * w0.w + a.y * w1.w + a.z * w2.w + a.w * w3.w;

// ---------------- iteration 1: gather(phase1) + block GEMM(phase2) --------------
__global__ __launch_bounds__(256) void k_iter1(const int* __restrict__ se,
                                               const int* __restrict__ bs,
                                               const float* __restrict__ fdg,
                                               const float* __restrict__ rij,
                                               const float* __restrict__ Wg) {
    __shared__ float4 sW[HH * 16];          // 16 KB  Wg
    __shared__ float4 sM[AD * 16];          // 2.5 KB M1
    __shared__ float  sacc[NPB][68];        // 17.4 KB aggregated neighbor feats
    __shared__ float  sax[NPB][12];         // 3 KB  aggregated edge feats
    __shared__ float4 sbc[8][2][17];        // 4.4 KB per-warp (alpha,idx,e) bcast

    int t = threadIdx.x, w = t >> 5, l = t & 31, sub = l & 15, half = l >> 4;
    for (int i = t; i < HH * 16; i += 256) sW[i] = ((const float4*)Wg)[i];
    for (int i = t; i < AD * 16; i += 256) sM[i] = d_M14[i];

    int blockBase = blockIdx.x * NPB;

    // ---- phase 1: gather + softmax, 2 nodes/warp, 4 rounds ----
    #pragma unroll 1
    for (int r = 0; r < RNDS; r++) {
        int rowLocal = r * 16 + w * 2 + half;
        int row = blockBase + rowLocal;
        bool live = (row >= 1) && (row <= NN);
        int idx = 0, eix = 0;
        float logit = NEGINF;
        if (live) {
            int n = row - 1;
            idx = se[n * KK + sub];
            eix = bs[n * KK + sub];
            float v = d_gp0[idx] + d_elog[eix];
            v = (v > 0.f) ? v : 0.2f * v;
            logit = (idx == 0) ? NEGINF : v;
        }
        float mx = logit;
        #pragma unroll
        for (int m = 8; m; m >>= 1) mx = fmaxf(mx, __shfl_xor_sync(0xffffffffu, mx, m, 16));
        float ex = __expf(logit - mx);
        float sum = ex;
        #pragma unroll
        for (int m = 8; m; m >>= 1) sum += __shfl_xor_sync(0xffffffffu, sum, m, 16);
        float alpha = ex / sum;

        sbc[w][half][sub] = make_float4(alpha, __int_as_float(idx), __int_as_float(eix), 0.f);
        __syncwarp();

        float4 acc = make_float4(0.f, 0.f, 0.f, 0.f);
        float ax = 0.f;
        #pragma unroll
        for (int k = 0; k < KK; k++) {
            float4 b = sbc[w][half][k];
            int i = __float_as_int(b.y);
            int e = __float_as_int(b.z);
            float4 v = d_hp0v[i * 16 + sub];
            acc.x += b.x * v.x; acc.y += b.x * v.y; acc.z += b.x * v.z; acc.w += b.x * v.w;
            if (sub < AD) {
                float x = (sub < FD) ? fdg[(long)e * FD + sub] : rij[e];
                ax += b.x * x;
            }
        }
        *(float4*)&sacc[rowLocal][sub * 4] = acc;
        if (sub < AD) sax[rowLocal][sub] = ax;
        __syncwarp();
    }
    __syncthreads();

    // ---- phase 2: [64 x 64] @ Wg + [64 x 10] @ M1, 4 nodes/thread ----
    int ch = t & 15, g = t >> 4;
    int nb = g * 4;
    float4 bm = d_bm4[ch];
    float4 o0 = bm, o1 = bm, o2 = bm, o3 = bm;
    #pragma unroll
    for (int s4 = 0; s4 < 16; s4++) {
        float4 w0 = sW[(4 * s4 + 0) * 16 + ch];
        float4 w1 = sW[(4 * s4 + 1) * 16 + ch];
        float4 w2 = sW[(4 * s4 + 2) * 16 + ch];
        float4 w3 = sW[(4 * s4 + 3) * 16 + ch];
        float4 a0 = *(float4*)&sacc[nb + 0][s4 * 4];
        float4 a1 = *(float4*)&sacc[nb + 1][s4 * 4];
        float4 a2 = *(float4*)&sacc[nb + 2][s4 * 4];
        float4 a3 = *(float4*)&sacc[nb + 3][s4 * 4];
        FMA4(o0, a0, w0, w1, w2, w3)
        FMA4(o1, a1, w0, w1, w2, w3)
        FMA4(o2, a2, w0, w1, w2, w3)
        FMA4(o3, a3, w0, w1, w2, w3)
    }
    #pragma unroll
    for (int rr = 0; rr < AD; rr++) {
        float4 m = sM[rr * 16 + ch];
        float x0 = sax[nb + 0][rr], x1 = sax[nb + 1][rr];
        float x2 = sax[nb + 2][rr], x3 = sax[nb + 3][rr];
        o0.x += x0 * m.x; o0.y += x0 * m.y; o0.z += x0 * m.z; o0.w += x0 * m.w;
        o1.x += x1 * m.x; o1.y += x1 * m.y; o1.z += x1 * m.z; o1.w += x1 * m.w;
        o2.x += x2 * m.x; o2.y += x2 * m.y; o2.z += x2 * m.z; o2.w += x2 * m.w;
        o3.x += x3 * m.x; o3.y += x3 * m.y; o3.z += x3 * m.z; o3.w += x3 * m.w;
    }
    #define ELU4(o) \
        o.x = (o.x > 0.f) ? o.x : expm1f(o.x); \
        o.y = (o.y > 0.f) ? o.y : expm1f(o.y); \
        o.z = (o.z > 0.f) ? o.z : expm1f(o.z); \
        o.w = (o.w > 0.f) ? o.w : expm1f(o.w);
    ELU4(o0) ELU4(o1) ELU4(o2) ELU4(o3)

    float4 p = d_p4[ch], q = d_q4[ch];
    float pp0 = o0.x*p.x + o0.y*p.y + o0.z*p.z + o0.w*p.w;
    float pp1 = o1.x*p.x + o1.y*p.y + o1.z*p.z + o1.w*p.w;
    float pp2 = o2.x*p.x + o2.y*p.y + o2.z*p.z + o2.w*p.w;
    float pp3 = o3.x*p.x + o3.y*p.y + o3.z*p.z + o3.w*p.w;
    float qq0 = o0.x*q.x + o0.y*q.y + o0.z*q.z + o0.w*q.w;
    float qq1 = o1.x*q.x + o1.y*q.y + o1.z*q.z + o1.w*q.w;
    float qq2 = o2.x*q.x + o2.y*q.y + o2.z*q.z + o2.w*q.w;
    float qq3 = o3.x*q.x + o3.y*q.y + o3.z*q.z + o3.w*q.w;
    #pragma unroll
    for (int m = 8; m; m >>= 1) {
        pp0 += __shfl_xor_sync(0xffffffffu, pp0, m, 16);
        pp1 += __shfl_xor_sync(0xffffffffu, pp1, m, 16);
        pp2 += __shfl_xor_sync(0xffffffffu, pp2, m, 16);
        pp3 += __shfl_xor_sync(0xffffffffu, pp3, m, 16);
        qq0 += __shfl_xor_sync(0xffffffffu, qq0, m, 16);
        qq1 += __shfl_xor_sync(0xffffffffu, qq1, m, 16);
        qq2 += __shfl_xor_sync(0xffffffffu, qq2, m, 16);
        qq3 += __shfl_xor_sync(0xffffffffu, qq3, m, 16);
    }
    #pragma unroll
    for (int i = 0; i < 4; i++) {
        int row = blockBase + nb + i;
        if (row > NN) continue;
        float4 o = (i == 0) ? o0 : (i == 1) ? o1 : (i == 2) ? o2 : o3;
        float pp = (i == 0) ? pp0 : (i == 1) ? pp1 : (i == 2) ? pp2 : pp3;
        float qq = (i == 0) ? qq0 : (i == 1) ? qq1 : (i == 2) ? qq2 : qq3;
        if (row == 0) { o = make_float4(0.f, 0.f, 0.f, 0.f); pp = 0.f; qq = 0.f; }
        d_hp1v[row * 16 + ch] = o;
        if (ch == 0) { d_gp1[row] = pp; d_gm1[row] = qq; }
    }
}

// ---------------- iteration 2 ---------------------------------------------------
__global__ __launch_bounds__(256) void k_iter2(const int* __restrict__ se,
                                               const int* __restrict__ bs,
                                               const int* __restrict__ su,
                                               const int* __restrict__ sul,
                                               const float* __restrict__ Wg,
                                               const float* __restrict__ Wm) {
    extern __shared__ float4 dyn[];
    float4* sWg = dyn;                              // 1024 float4 = 16 KB
    float4* sWm = dyn + 1024;                       // 16 KB
    float*  saccA = (float*)(dyn + 2048);           // NPB*68 floats = 17.4 KB
    float*  saccB = saccA + NPB * 68;               // 17.4 KB
    float4* sbc = (float4*)(saccB + NPB * 68);      // 8*2*17 float4 = 4.4 KB

    int t = threadIdx.x, w = t >> 5, l = t & 31, sub = l & 15, half = l >> 4;
    for (int i = t; i < HH * 16; i += 256) {
        sWg[i] = ((const float4*)Wg)[i];
        sWm[i] = ((const float4*)Wm)[i];
    }

    int blockBase = blockIdx.x * NPB;

    // ---- phase 1 ----
    #pragma unroll 1
    for (int r = 0; r < RNDS; r++) {
        int rowLocal = r * 16 + w * 2 + half;
        int row = blockBase + rowLocal;
        bool live = (row >= 1) && (row <= NN);
        int idx = 0, j = 0;
        float msk = 0.f, logit = NEGINF;
        if (live) {
            int n = row - 1;
            idx = se[n * KK + sub];
            int e = bs[n * KK + sub];
            j = su[e];
            msk = (sul[e] > 0) ? 1.f : 0.f;
            float v = d_gp1[idx] + msk * d_gm1[j];
            v = (v > 0.f) ? v : 0.2f * v;
            logit = (idx == 0) ? NEGINF : v;
        }
        float mx = logit;
        #pragma unroll
        for (int m = 8; m; m >>= 1) mx = fmaxf(mx, __shfl_xor_sync(0xffffffffu, mx, m, 16));
        float ex = __expf(logit - mx);
        float sum = ex;
        #pragma unroll
        for (int m = 8; m; m >>= 1) sum += __shfl_xor_sync(0xffffffffu, sum, m, 16);
        float alpha = ex / sum;

        sbc[(w * 2 + half) * 17 + sub] = make_float4(alpha, __int_as_float(idx),
                                                     __int_as_float(j), msk);
        __syncwarp();

        float4 accA = make_float4(0.f, 0.f, 0.f, 0.f);
        float4 accB = make_float4(0.f, 0.f, 0.f, 0.f);
        #pragma unroll
        for (int k = 0; k < KK; k++) {
            float4 b = sbc[(w * 2 + half) * 17 + k];
            int i  = __float_as_int(b.y);
            int jj = __float_as_int(b.z);
            float4 v = d_hp1v[i * 16 + sub];
            accA.x += b.x * v.x; accA.y += b.x * v.y; accA.z += b.x * v.z; accA.w += b.x * v.w;
            float am = b.x * b.w;
            float4 u = d_hp1v[jj * 16 + sub];
            accB.x += am * u.x; accB.y += am * u.y; accB.z += am * u.z; accB.w += am * u.w;
        }
        *(float4*)&saccA[rowLocal * 68 + sub * 4] = accA;
        *(float4*)&saccB[rowLocal * 68 + sub * 4] = accB;
        __syncwarp();
    }
    __syncthreads();

    // ---- phase 2: [64x64]@Wg + [64x64]@Wm ----
    int ch = t & 15, g = t >> 4;
    int nb = g * 4;
    float4 o0 = make_float4(0.f,0.f,0.f,0.f), o1 = o0, o2 = o0, o3 = o0;
    #pragma unroll
    for (int s4 = 0; s4 < 16; s4++) {
        {
            float4 w0 = sWg[(4 * s4 + 0) * 16 + ch];
            float4 w1 = sWg[(4 * s4 + 1) * 16 + ch];
            float4 w2 = sWg[(4 * s4 + 2) * 16 + ch];
            float4 w3 = sWg[(4 * s4 + 3) * 16 + ch];
            float4 a0 = *(float4*)&saccA[(nb + 0) * 68 + s4 * 4];
            float4 a1 = *(float4*)&saccA[(nb + 1) * 68 + s4 * 4];
            float4 a2 = *(float4*)&saccA[(nb + 2) * 68 + s4 * 4];
            float4 a3 = *(float4*)&saccA[(nb + 3) * 68 + s4 * 4];
            FMA4(o0, a0, w0, w1, w2, w3)
            FMA4(o1, a1, w0, w1, w2, w3)
            FMA4(o2, a2, w0, w1, w2, w3)
            FMA4(o3, a3, w0, w1, w2, w3)
        }
        {
            float4 w0 = sWm[(4 * s4 + 0) * 16 + ch];
            float4 w1 = sWm[(4 * s4 + 1) * 16 + ch];
            float4 w2 = sWm[(4 * s4 + 2) * 16 + ch];
            float4 w3 = sWm[(4 * s4 + 3) * 16 + ch];
            float4 b0 = *(float4*)&saccB[(nb + 0) * 68 + s4 * 4];
            float4 b1 = *(float4*)&saccB[(nb + 1) * 68 + s4 * 4];
            float4 b2 = *(float4*)&saccB[(nb + 2) * 68 + s4 * 4];
            float4 b3 = *(float4*)&saccB[(nb + 3) * 68 + s4 * 4];
            FMA4(o0, b0, w0, w1, w2, w3)
            FMA4(o1, b1, w0, w1, w2, w3)
            FMA4(o2, b2, w0, w1, w2, w3)
            FMA4(o3, b3, w0, w1, w2, w3)
        }
    }
    ELU4(o0) ELU4(o1) ELU4(o2) ELU4(o3)
    #pragma unroll
    for (int i = 0; i < 4; i++) {
        int row = blockBase + nb + i;
        if (row > NN) continue;
        float4 o = (i == 0) ? o0 : (i == 1) ? o1 : (i == 2) ? o2 : o3;
        if (row == 0) o = make_float4(0.f, 0.f, 0.f, 0.f);
        d_hp2v[row * 16 + ch] = o;
    }
}

// ---------------- readout -------------------------------------------------------
__global__ __launch_bounds__(256) void k_out(const int* __restrict__ ls,
                                             float* __restrict__ out) {
    int wid = (blockIdx.x * blockDim.x + threadIdx.x) >> 5;
    int l = threadIdx.x & 31;
    int sub = l & 15;
    int mol = wid * 2 + (l >> 4);
    if (mol >= BBATCH) return;
    const int* row = ls + mol * MAXM;
    float4 acc = make_float4(0.f, 0.f, 0.f, 0.f);
    #pragma unroll 8
    for (int m = 0; m < MAXM; m++) {
        int i = __ldg(row + m);
        float4 v = d_hp2v[i * 16 + sub];
        acc.x += v.x; acc.y += v.y; acc.z += v.z; acc.w += v.w;
    }
    ((float4*)out)[mol * 16 + sub] = acc;
}

// ---------------- launch --------------------------------------------------------
extern "C" void kernel_launch(void* const* d_in, const int* in_sizes, int n_in,
                              void* d_out, int out_size) {
    const float* tf  = (const float*)d_in[0];
    const float* fdg = (const float*)d_in[1];
    const float* rij = (const float*)d_in[2];
    const int*   se  = (const int*)d_in[3];
    const int*   bs  = (const int*)d_in[4];
    const int*   ls  = (const int*)d_in[5];
    const int*   su  = (const int*)d_in[6];
    const int*   sul = (const int*)d_in[7];
    const float* We  = (const float*)d_in[8];
    const float* be  = (const float*)d_in[9];
    const float* Wd  = (const float*)d_in[10];
    const float* bd  = (const float*)d_in[11];
    const float* Wg  = (const float*)d_in[12];
    const float* Wm  = (const float*)d_in[13];
    const float* ag  = (const float*)d_in[14];

    static int smem_set = 0;
    int it2_smem = (2048 * 16) + 2 * NPB * 68 * 4 + 8 * 2 * 17 * 16;  // 71936 B
    if (!smem_set) {
        cudaFuncSetAttribute(k_iter2, cudaFuncAttributeMaxDynamicSharedMemorySize, it2_smem);
        smem_set = 1;
    }

    int embed_warps = (NN + 2) / 2;
    int embed_blocks = (embed_warps + 7) / 8;
    int NB = (NN + 1 + NPB - 1) / NPB;   // 782 blocks of 64 node-rows

    k_consts<<<1, 64>>>(Wg, Wm, ag, Wd, bd);
    k_embed<<<embed_blocks, 256>>>(tf, We, be);
    k_elog<<<(EE + 255) / 256, 256>>>(fdg, rij);
    k_iter1<<<NB, 256>>>(se, bs, fdg, rij, Wg);
    k_iter2<<<NB, 256, it2_smem>>>(se, bs, su, sul, Wg, Wm);
    k_out<<<(BBATCH / 2 + 7) / 8, 256>>>(ls, (float*)d_out);
}

// round 4
// speedup vs baseline: 2.1513x; 1.0546x over previous
#include <cuda_runtime.h>
#include <math.h>

#define NN 50000
#define KK 16
#define EE 800000
#define BBATCH 1024
#define MAXM 48
#define FD 9
#define AD 10
#define HH 64
#define NEGINF (-1e9f)

// ---------------- scratch ------------------------------------------------------
__device__ float4 d_hp0v[(NN + 1) * 16];
__device__ float4 d_hp1v[(NN + 1) * 16];
__device__ float4 d_hp2v[(NN + 1) * 16];
__device__ float d_gp0[NN + 1];
__device__ float d_gp1[NN + 1];
__device__ float d_gm1[NN + 1];
__device__ float d_elog[EE];
__device__ float d_alpha[NN * KK];
__device__ float d_alpham[NN * KK];
__device__ int   d_j[NN * KK];
__device__ float4 d_accAv[NN * 16];
__device__ float4 d_accBv[NN * 16];
__device__ float d_accX16[NN * 16];
__device__ float4 d_p4[16];
__device__ float4 d_q4[16];
__device__ float d_qd[AD];
__device__ float d_c;
__device__ float4 d_M14[AD * 16];
__device__ float4 d_bm4[16];

// ---------------- small constants ----------------------------------------------
__global__ void k_consts(const float* __restrict__ Wg, const float* __restrict__ Wm,
                         const float* __restrict__ a,  const float* __restrict__ Wd,
                         const float* __restrict__ bd) {
    int j = threadIdx.x;  // 0..63
    float p = 0.f, q = 0.f;
    #pragma unroll 8
    for (int t = 0; t < HH; t++) {
        p += Wg[j * HH + t] * a[t];
        q += Wm[j * HH + t] * a[HH + t];
    }
    ((float*)d_p4)[j] = p;
    ((float*)d_q4)[j] = q;
    __shared__ float sq[HH];
    sq[j] = q;
    __syncthreads();
    if (j < AD) {
        float s = 0.f;
        for (int t = 0; t < HH; t++) s += Wd[j * HH + t] * sq[t];
        d_qd[j] = s;
    }
    if (j == 0) {
        float s = 0.f;
        for (int t = 0; t < HH; t++) s += bd[t] * sq[t];
        d_c = s;
    }
    for (int r = 0; r < AD; r++) {
        float s = 0.f;
        for (int i = 0; i < HH; i++) s += Wd[r * HH + i] * Wm[i * HH + j];
        ((float*)d_M14)[r * HH + j] = s;
    }
    float s = 0.f;
    for (int i = 0; i < HH; i++) s += bd[i] * Wm[i * HH + j];
    ((float*)d_bm4)[j] = s;
}

// ---------------- node embedding + gp0 ------------------------------------------
__global__ __launch_bounds__(256) void k_embed(const float* __restrict__ tf,
                                               const float* __restrict__ We,
                                               const float* __restrict__ be) {
    int wid = (blockIdx.x * blockDim.x + threadIdx.x) >> 5;
    int l = threadIdx.x & 31;
    int sub = l & 15;
    int row = wid * 2 + (l >> 4);
    if (row > NN) return;
    float4 acc = make_float4(0.f, 0.f, 0.f, 0.f);
    if (row > 0) {
        int n = row - 1;
        const float* r = tf + n * FD;
        acc = ((const float4*)be)[sub];
        #pragma unroll
        for (int t = 0; t < FD; t++) {
            float x = __ldg(r + t);
            float4 w = ((const float4*)We)[t * 16 + sub];
            acc.x += x * w.x; acc.y += x * w.y; acc.z += x * w.z; acc.w += x * w.w;
        }
    }
    d_hp0v[row * 16 + sub] = acc;
    float4 p = d_p4[sub];
    float pp = acc.x * p.x + acc.y * p.y + acc.z * p.z + acc.w * p.w;
    #pragma unroll
    for (int m = 8; m; m >>= 1) pp += __shfl_xor_sync(0xffffffffu, pp, m, 16);
    if (sub == 0) d_gp0[row] = pp;
}

// ---------------- per-edge logit scalar ------------------------------------------
__global__ void k_elog(const float* __restrict__ fdg, const float* __restrict__ rij) {
    int e = blockIdx.x * blockDim.x + threadIdx.x;
    if (e >= EE) return;
    float s = d_c + rij[e] * d_qd[9];
    const float* x = fdg + (long)e * FD;
    #pragma unroll
    for (int r = 0; r < FD; r++) s += x[r] * d_qd[r];
    d_elog[e] = s;
}

// ---------------- softmax helper (width 16) --------------------------------------
__device__ __forceinline__ float softmax16(float logit) {
    float mx = logit;
    #pragma unroll
    for (int m = 8; m; m >>= 1) mx = fmaxf(mx, __shfl_xor_sync(0xffffffffu, mx, m, 16));
    float ex = __expf(logit - mx);
    float sum = ex;
    #pragma unroll
    for (int m = 8; m; m >>= 1) sum += __shfl_xor_sync(0xffffffffu, sum, m, 16);
    return ex / sum;
}

// ---------------- alpha, iteration 1 (1 thread per (n,k)) ------------------------
__global__ __launch_bounds__(256) void k_alpha1(const int* __restrict__ se,
                                                const int* __restrict__ bs) {
    int t = blockIdx.x * blockDim.x + threadIdx.x;   // < NN*16
    int idx = se[t];
    int e   = bs[t];
    float v = d_gp0[idx] + d_elog[e];
    v = (v > 0.f) ? v : 0.2f * v;
    float logit = (idx == 0) ? NEGINF : v;
    d_alpha[t] = softmax16(logit);
}

// ---------------- alpha, iteration 2 ---------------------------------------------
__global__ __launch_bounds__(256) void k_alpha2(const int* __restrict__ se,
                                                const int* __restrict__ bs,
                                                const int* __restrict__ su,
                                                const int* __restrict__ sul) {
    int t = blockIdx.x * blockDim.x + threadIdx.x;
    int idx = se[t];
    int e   = bs[t];
    int j   = su[e];
    float msk = (sul[e] > 0) ? 1.f : 0.f;
    float v = d_gp1[idx] + msk * d_gm1[j];
    v = (v > 0.f) ? v : 0.2f * v;
    float logit = (idx == 0) ? NEGINF : v;
    float alpha = softmax16(logit);
    d_alpha[t]  = alpha;
    d_alpham[t] = alpha * msk;
    d_j[t]      = j;
}

// ---------------- gather, iteration 1 (half-warp per node) ------------------------
__global__ __launch_bounds__(256) void k_gather1(const int* __restrict__ se,
                                                 const int* __restrict__ bs,
                                                 const float* __restrict__ fdg,
                                                 const float* __restrict__ rij) {
    __shared__ float4 sbc[8][2][17];
    int t = threadIdx.x, w = t >> 5, l = t & 31, sub = l & 15, half = l >> 4;
    int n = (blockIdx.x * 8 + w) * 2 + half;         // node id, < NN exactly

    float a = d_alpha[n * KK + sub];
    int idx = se[n * KK + sub];
    int e   = bs[n * KK + sub];
    sbc[w][half][sub] = make_float4(a, __int_as_float(idx), __int_as_float(e), 0.f);
    __syncwarp();

    float4 acc = make_float4(0.f, 0.f, 0.f, 0.f);
    float ax = 0.f;
    #pragma unroll
    for (int k = 0; k < KK; k++) {
        float4 b = sbc[w][half][k];
        int i  = __float_as_int(b.y);
        int ee = __float_as_int(b.z);
        float4 v = d_hp0v[i * 16 + sub];
        acc.x += b.x * v.x; acc.y += b.x * v.y; acc.z += b.x * v.z; acc.w += b.x * v.w;
        if (sub < AD) {
            float x = (sub < FD) ? fdg[(long)ee * FD + sub] : rij[ee];
            ax += b.x * x;
        }
    }
    d_accAv[n * 16 + sub] = acc;
    d_accX16[n * 16 + sub] = ax;
}

// ---------------- gather, iteration 2 ---------------------------------------------
__global__ __launch_bounds__(256) void k_gather2(const int* __restrict__ se) {
    __shared__ float4 sbc[8][2][17];
    int t = threadIdx.x, w = t >> 5, l = t & 31, sub = l & 15, half = l >> 4;
    int n = (blockIdx.x * 8 + w) * 2 + half;

    float a  = d_alpha[n * KK + sub];
    float am = d_alpham[n * KK + sub];
    int idx  = se[n * KK + sub];
    int j    = d_j[n * KK + sub];
    sbc[w][half][sub] = make_float4(a, __int_as_float(idx), __int_as_float(j), am);
    __syncwarp();

    float4 accA = make_float4(0.f, 0.f, 0.f, 0.f);
    float4 accB = make_float4(0.f, 0.f, 0.f, 0.f);
    #pragma unroll
    for (int k = 0; k < KK; k++) {
        float4 b = sbc[w][half][k];
        int i  = __float_as_int(b.y);
        int jj = __float_as_int(b.z);
        float4 v = d_hp1v[i * 16 + sub];
        accA.x += b.x * v.x; accA.y += b.x * v.y; accA.z += b.x * v.z; accA.w += b.x * v.w;
        float4 u = d_hp1v[jj * 16 + sub];
        accB.x += b.w * u.x; accB.y += b.w * u.y; accB.z += b.w * u.z; accB.w += b.w * u.w;
    }
    d_accAv[n * 16 + sub] = accA;
    d_accBv[n * 16 + sub] = accB;
}

#define FMA4(o, a, w0, w1, w2, w3)                                     \
    o.x += a.x * w0.x + a.y * w1.x + a.z * w2.x + a.w * w3.x;          \
    o.y += a.x * w0.y + a.y * w1.y + a.z * w2.y + a.w * w3.y;          \
    o.z += a.x * w0.z + a.y * w1.z + a.z * w2.z + a.w * w3.z;          \
    o.w += a.x * w0.w + a.y * w1.w + a.z * w2.w + a.w * w3.w;

#define ELU4(o) \
    o.x = (o.x > 0.f) ? o.x : expm1f(o.x); \
    o.y = (o.y > 0.f) ? o.y : expm1f(o.y); \
    o.z = (o.z > 0.f) ? o.z : expm1f(o.z); \
    o.w = (o.w > 0.f) ? o.w : expm1f(o.w);

// ---------------- GEMM, iteration 1 (64 nodes per block) ---------------------------
__global__ __launch_bounds__(256) void k_gemm1(const float* __restrict__ Wg) {
    __shared__ float4 sW[HH * 16];      // 16 KB
    __shared__ float4 sM[AD * 16];      // 2.5 KB
    __shared__ float  sacc[64][68];     // 17.4 KB
    __shared__ float  sax[64 * 17];     // 4.3 KB
    int t = threadIdx.x;
    int nb0 = blockIdx.x * 64;
    for (int i = t; i < HH * 16; i += 256) sW[i] = ((const float4*)Wg)[i];
    for (int i = t; i < AD * 16; i += 256) sM[i] = d_M14[i];
    for (int i = t; i < 1024; i += 256) {
        int node = i >> 4, s = i & 15, n = nb0 + node;
        float4 v = (n < NN) ? d_accAv[n * 16 + s] : make_float4(0.f, 0.f, 0.f, 0.f);
        *(float4*)&sacc[node][s * 4] = v;
    }
    for (int i = t; i < 1024; i += 256) {
        int node = i >> 4, r = i & 15, n = nb0 + node;
        sax[node * 17 + r] = (n < NN) ? d_accX16[n * 16 + r] : 0.f;
    }
    __syncthreads();

    int ch = t & 15, g = t >> 4;
    int nl = g * 4;
    float4 bm = d_bm4[ch];
    float4 o0 = bm, o1 = bm, o2 = bm, o3 = bm;
    #pragma unroll
    for (int s4 = 0; s4 < 16; s4++) {
        float4 w0 = sW[(4 * s4 + 0) * 16 + ch];
        float4 w1 = sW[(4 * s4 + 1) * 16 + ch];
        float4 w2 = sW[(4 * s4 + 2) * 16 + ch];
        float4 w3 = sW[(4 * s4 + 3) * 16 + ch];
        float4 a0 = *(float4*)&sacc[nl + 0][s4 * 4];
        float4 a1 = *(float4*)&sacc[nl + 1][s4 * 4];
        float4 a2 = *(float4*)&sacc[nl + 2][s4 * 4];
        float4 a3 = *(float4*)&sacc[nl + 3][s4 * 4];
        FMA4(o0, a0, w0, w1, w2, w3)
        FMA4(o1, a1, w0, w1, w2, w3)
        FMA4(o2, a2, w0, w1, w2, w3)
        FMA4(o3, a3, w0, w1, w2, w3)
    }
    #pragma unroll
    for (int rr = 0; rr < AD; rr++) {
        float4 m = sM[rr * 16 + ch];
        float x0 = sax[(nl + 0) * 17 + rr], x1 = sax[(nl + 1) * 17 + rr];
        float x2 = sax[(nl + 2) * 17 + rr], x3 = sax[(nl + 3) * 17 + rr];
        o0.x += x0 * m.x; o0.y += x0 * m.y; o0.z += x0 * m.z; o0.w += x0 * m.w;
        o1.x += x1 * m.x; o1.y += x1 * m.y; o1.z += x1 * m.z; o1.w += x1 * m.w;
        o2.x += x2 * m.x; o2.y += x2 * m.y; o2.z += x2 * m.z; o2.w += x2 * m.w;
        o3.x += x3 * m.x; o3.y += x3 * m.y; o3.z += x3 * m.z; o3.w += x3 * m.w;
    }
    ELU4(o0) ELU4(o1) ELU4(o2) ELU4(o3)

    float4 p = d_p4[ch], q = d_q4[ch];
    float pp0 = o0.x*p.x + o0.y*p.y + o0.z*p.z + o0.w*p.w;
    float pp1 = o1.x*p.x + o1.y*p.y + o1.z*p.z + o1.w*p.w;
    float pp2 = o2.x*p.x + o2.y*p.y + o2.z*p.z + o2.w*p.w;
    float pp3 = o3.x*p.x + o3.y*p.y + o3.z*p.z + o3.w*p.w;
    float qq0 = o0.x*q.x + o0.y*q.y + o0.z*q.z + o0.w*q.w;
    float qq1 = o1.x*q.x + o1.y*q.y + o1.z*q.z + o1.w*q.w;
    float qq2 = o2.x*q.x + o2.y*q.y + o2.z*q.z + o2.w*q.w;
    float qq3 = o3.x*q.x + o3.y*q.y + o3.z*q.z + o3.w*q.w;
    #pragma unroll
    for (int m = 8; m; m >>= 1) {
        pp0 += __shfl_xor_sync(0xffffffffu, pp0, m, 16);
        pp1 += __shfl_xor_sync(0xffffffffu, pp1, m, 16);
        pp2 += __shfl_xor_sync(0xffffffffu, pp2, m, 16);
        pp3 += __shfl_xor_sync(0xffffffffu, pp3, m, 16);
        qq0 += __shfl_xor_sync(0xffffffffu, qq0, m, 16);
        qq1 += __shfl_xor_sync(0xffffffffu, qq1, m, 16);
        qq2 += __shfl_xor_sync(0xffffffffu, qq2, m, 16);
        qq3 += __shfl_xor_sync(0xffffffffu, qq3, m, 16);
    }
    #pragma unroll
    for (int i = 0; i < 4; i++) {
        int n = nb0 + nl + i;
        if (n >= NN) continue;
        int row = n + 1;
        float4 o = (i == 0) ? o0 : (i == 1) ? o1 : (i == 2) ? o2 : o3;
        float pp = (i == 0) ? pp0 : (i == 1) ? pp1 : (i == 2) ? pp2 : pp3;
        float qq = (i == 0) ? qq0 : (i == 1) ? qq1 : (i == 2) ? qq2 : qq3;
        d_hp1v[row * 16 + ch] = o;
        if (ch == 0) { d_gp1[row] = pp; d_gm1[row] = qq; }
    }
    if (blockIdx.x == 0 && t < 16) d_hp1v[t] = make_float4(0.f, 0.f, 0.f, 0.f);
    if (blockIdx.x == 0 && t == 0) { d_gp1[0] = 0.f; d_gm1[0] = 0.f; }
}

// ---------------- GEMM, iteration 2 ------------------------------------------------
__global__ __launch_bounds__(256) void k_gemm2(const float* __restrict__ Wg,
                                               const float* __restrict__ Wm) {
    __shared__ float4 sW[HH * 16];      // 16 KB (reused Wg then Wm)
    __shared__ float  sacc[64][68];     // 17.4 KB (reused A then B)
    int t = threadIdx.x;
    int nb0 = blockIdx.x * 64;
    int ch = t & 15, g = t >> 4;
    int nl = g * 4;
    float4 o0 = make_float4(0.f,0.f,0.f,0.f), o1 = o0, o2 = o0, o3 = o0;

    for (int pass = 0; pass < 2; pass++) {
        const float4* W = (pass == 0) ? (const float4*)Wg : (const float4*)Wm;
        const float4* A = (pass == 0) ? d_accAv : d_accBv;
        for (int i = t; i < HH * 16; i += 256) sW[i] = W[i];
        for (int i = t; i < 1024; i += 256) {
            int node = i >> 4, s = i & 15, n = nb0 + node;
            float4 v = (n < NN) ? A[n * 16 + s] : make_float4(0.f, 0.f, 0.f, 0.f);
            *(float4*)&sacc[node][s * 4] = v;
        }
        __syncthreads();
        #pragma unroll
        for (int s4 = 0; s4 < 16; s4++) {
            float4 w0 = sW[(4 * s4 + 0) * 16 + ch];
            float4 w1 = sW[(4 * s4 + 1) * 16 + ch];
            float4 w2 = sW[(4 * s4 + 2) * 16 + ch];
            float4 w3 = sW[(4 * s4 + 3) * 16 + ch];
            float4 a0 = *(float4*)&sacc[nl + 0][s4 * 4];
            float4 a1 = *(float4*)&sacc[nl + 1][s4 * 4];
            float4 a2 = *(float4*)&sacc[nl + 2][s4 * 4];
            float4 a3 = *(float4*)&sacc[nl + 3][s4 * 4];
            FMA4(o0, a0, w0, w1, w2, w3)
            FMA4(o1, a1, w0, w1, w2, w3)
            FMA4(o2, a2, w0, w1, w2, w3)
            FMA4(o3, a3, w0, w1, w2, w3)
        }
        __syncthreads();
    }
    ELU4(o0) ELU4(o1) ELU4(o2) ELU4(o3)
    #pragma unroll
    for (int i = 0; i < 4; i++) {
        int n = nb0 + nl + i;
        if (n >= NN) continue;
        float4 o = (i == 0) ? o0 : (i == 1) ? o1 : (i == 2) ? o2 : o3;
        d_hp2v[(n + 1) * 16 + ch] = o;
    }
    if (blockIdx.x == 0 && t < 16) d_hp2v[t] = make_float4(0.f, 0.f, 0.f, 0.f);
}

// ---------------- readout ----------------------------------------------------------
__global__ __launch_bounds__(256) void k_out(const int* __restrict__ ls,
                                             float* __restrict__ out) {
    int wid = (blockIdx.x * blockDim.x + threadIdx.x) >> 5;
    int l = threadIdx.x & 31;
    int sub = l & 15;
    int mol = wid * 2 + (l >> 4);
    if (mol >= BBATCH) return;
    const int* row = ls + mol * MAXM;
    float4 acc = make_float4(0.f, 0.f, 0.f, 0.f);
    #pragma unroll 8
    for (int m = 0; m < MAXM; m++) {
        int i = __ldg(row + m);
        float4 v = d_hp2v[i * 16 + sub];
        acc.x += v.x; acc.y += v.y; acc.z += v.z; acc.w += v.w;
    }
    ((float4*)out)[mol * 16 + sub] = acc;
}

// ---------------- launch -----------------------------------------------------------
extern "C" void kernel_launch(void* const* d_in, const int* in_sizes, int n_in,
                              void* d_out, int out_size) {
    const float* tf  = (const float*)d_in[0];
    const float* fdg = (const float*)d_in[1];
    const float* rij = (const float*)d_in[2];
    const int*   se  = (const int*)d_in[3];
    const int*   bs  = (const int*)d_in[4];
    const int*   ls  = (const int*)d_in[5];
    const int*   su  = (const int*)d_in[6];
    const int*   sul = (const int*)d_in[7];
    const float* We  = (const float*)d_in[8];
    const float* be  = (const float*)d_in[9];
    const float* Wd  = (const float*)d_in[10];
    const float* bd  = (const float*)d_in[11];
    const float* Wg  = (const float*)d_in[12];
    const float* Wm  = (const float*)d_in[13];
    const float* ag  = (const float*)d_in[14];

    int embed_warps = (NN + 2) / 2;
    int embed_blocks = (embed_warps + 7) / 8;
    int nk_blocks = (NN * KK) / 256;        // 3125
    int gat_blocks = NN / 16;               // 3125 (16 nodes / block)
    int gemm_blocks = (NN + 63) / 64;       // 782

    k_consts<<<1, 64>>>(Wg, Wm, ag, Wd, bd);
    k_embed<<<embed_blocks, 256>>>(tf, We, be);
    k_elog<<<(EE + 255) / 256, 256>>>(fdg, rij);

    k_alpha1<<<nk_blocks, 256>>>(se, bs);
    k_gather1<<<gat_blocks, 256>>>(se, bs, fdg, rij);
    k_gemm1<<<gemm_blocks, 256>>>(Wg);

    k_alpha2<<<nk_blocks, 256>>>(se, bs, su, sul);
    k_gather2<<<gat_blocks, 256>>>(se);
    k_gemm2<<<gemm_blocks, 256>>>(Wg, Wm);

    k_out<<<(BBATCH / 2 + 7) / 8, 256>>>(ls, (float*)d_out);
}

// round 5
// speedup vs baseline: 2.2788x; 1.0593x over previous
#include <cuda_runtime.h>
#include <math.h>

#define NN 50000
#define KK 16
#define EE 800000
#define BBATCH 1024
#define MAXM 48
#define FD 9
#define AD 10
#define HH 64
#define NEGINF (-1e9f)
#define NB_EMB 3126              // ceil((NN+1)/16)
#define NB_ELOG 3125             // EE/256

// ---------------- scratch ------------------------------------------------------
__device__ float4 d_hp0v[(NN + 1) * 16];
__device__ float4 d_hp1v[(NN + 1) * 16];
__device__ float4 d_hp2v[(NN + 1) * 16];
__device__ float d_gp0[NN + 1];
__device__ float d_gp1[NN + 1];
__device__ float d_gm1[NN + 1];
__device__ float d_elog[EE];
__device__ float4 d_accAv[NN * 16];
__device__ float4 d_accBv[NN * 16];
__device__ float d_accX16[NN * 16];
__device__ float4 d_p4[16];
__device__ float4 d_q4[16];
__device__ float d_qd[AD];
__device__ float d_c;
__device__ float d_wep[FD];      // We @ p
__device__ float d_c0;           // be . p
__device__ float4 d_M14[AD * 16];
__device__ float4 d_bm4[16];

// ---------------- constants (1 block, 256 threads) ------------------------------
__global__ __launch_bounds__(256) void k_consts(const float* __restrict__ Wg,
                                                const float* __restrict__ Wm,
                                                const float* __restrict__ a,
                                                const float* __restrict__ Wd,
                                                const float* __restrict__ bd,
                                                const float* __restrict__ We,
                                                const float* __restrict__ be) {
    __shared__ float sp[HH], sq[HH];
    int t = threadIdx.x;
    if (t < HH) {
        float p = 0.f, q = 0.f;
        #pragma unroll 8
        for (int i = 0; i < HH; i++) {
            p += Wg[t * HH + i] * a[i];
            q += Wm[t * HH + i] * a[HH + i];
        }
        sp[t] = p; sq[t] = q;
        ((float*)d_p4)[t] = p;
        ((float*)d_q4)[t] = q;
    }
    __syncthreads();
    if (t < AD) {
        float s = 0.f;
        for (int i = 0; i < HH; i++) s += Wd[t * HH + i] * sq[i];
        d_qd[t] = s;
    } else if (t == AD) {
        float s = 0.f;
        for (int i = 0; i < HH; i++) s += bd[i] * sq[i];
        d_c = s;
    } else if (t >= 32 && t < 32 + FD) {
        int r = t - 32;
        float s = 0.f;
        for (int j = 0; j < HH; j++) s += We[r * HH + j] * sp[j];
        d_wep[r] = s;
    } else if (t == 32 + FD) {
        float s = 0.f;
        for (int j = 0; j < HH; j++) s += be[j] * sp[j];
        d_c0 = s;
    }
    // M14[r][j] = Wd row r . Wm col j   (640 entries)
    for (int idx = t; idx < AD * HH; idx += 256) {
        int r = idx >> 6, j = idx & 63;
        float s = 0.f;
        #pragma unroll 8
        for (int i = 0; i < HH; i++) s += Wd[r * HH + i] * Wm[i * HH + j];
        ((float*)d_M14)[idx] = s;
    }
    if (t < HH) {
        float s = 0.f;
        for (int i = 0; i < HH; i++) s += bd[i] * Wm[i * HH + t];
        ((float*)d_bm4)[t] = s;
    }
}

// ---------------- fused embed (+gp0) and per-edge logit --------------------------
__global__ __launch_bounds__(256) void k_pre(const float* __restrict__ tf,
                                             const float* __restrict__ We,
                                             const float* __restrict__ be,
                                             const float* __restrict__ fdg,
                                             const float* __restrict__ rij) {
    int b = blockIdx.x;
    if (b < NB_EMB) {
        int t = threadIdx.x, w = t >> 5, l = t & 31, sub = l & 15, half = l >> 4;
        int row = b * 16 + w * 2 + half;
        if (row > NN) return;
        float4 acc = make_float4(0.f, 0.f, 0.f, 0.f);
        float g = 0.f;
        if (row > 0) {
            int n = row - 1;
            const float* r = tf + n * FD;
            acc = ((const float4*)be)[sub];
            g = d_c0;
            #pragma unroll
            for (int tt = 0; tt < FD; tt++) {
                float x = __ldg(r + tt);
                float4 ww = ((const float4*)We)[tt * 16 + sub];
                acc.x += x * ww.x; acc.y += x * ww.y; acc.z += x * ww.z; acc.w += x * ww.w;
                g += x * d_wep[tt];
            }
        }
        d_hp0v[row * 16 + sub] = acc;
        if (sub == 0) d_gp0[row] = g;
    } else {
        int e = (b - NB_EMB) * 256 + threadIdx.x;
        if (e >= EE) return;
        float s = d_c + rij[e] * d_qd[9];
        const float* x = fdg + (long)e * FD;
        #pragma unroll
        for (int r = 0; r < FD; r++) s += x[r] * d_qd[r];
        d_elog[e] = s;
    }
}

// ---------------- softmax helper (width 16) --------------------------------------
__device__ __forceinline__ float softmax16(float logit) {
    float mx = logit;
    #pragma unroll
    for (int m = 8; m; m >>= 1) mx = fmaxf(mx, __shfl_xor_sync(0xffffffffu, mx, m, 16));
    float ex = __expf(logit - mx);
    float sum = ex;
    #pragma unroll
    for (int m = 8; m; m >>= 1) sum += __shfl_xor_sync(0xffffffffu, sum, m, 16);
    return ex / sum;
}

// ---------------- fused alpha + gather, iteration 1 ------------------------------
__global__ __launch_bounds__(256) void k_gather1(const int* __restrict__ se,
                                                 const int* __restrict__ bs,
                                                 const float* __restrict__ fdg,
                                                 const float* __restrict__ rij) {
    __shared__ float4 sbc[8][2][17];
    int t = threadIdx.x, w = t >> 5, l = t & 31, sub = l & 15, half = l >> 4;
    int n = (blockIdx.x * 8 + w) * 2 + half;     // < NN exactly

    int idx = se[n * KK + sub];
    int e   = bs[n * KK + sub];
    float v = __ldg(&d_gp0[idx]) + __ldg(&d_elog[e]);
    v = (v > 0.f) ? v : 0.2f * v;
    float alpha = softmax16((idx == 0) ? NEGINF : v);

    sbc[w][half][sub] = make_float4(alpha, __int_as_float(idx), __int_as_float(e), 0.f);
    __syncwarp();

    float4 acc = make_float4(0.f, 0.f, 0.f, 0.f);
    float ax = 0.f;
    #pragma unroll
    for (int k = 0; k < KK; k++) {
        float4 b = sbc[w][half][k];
        int i  = __float_as_int(b.y);
        int ee = __float_as_int(b.z);
        float4 vv = d_hp0v[i * 16 + sub];
        acc.x += b.x * vv.x; acc.y += b.x * vv.y; acc.z += b.x * vv.z; acc.w += b.x * vv.w;
        if (sub < AD) {
            float x = (sub < FD) ? fdg[(long)ee * FD + sub] : rij[ee];
            ax += b.x * x;
        }
    }
    d_accAv[n * 16 + sub] = acc;
    d_accX16[n * 16 + sub] = ax;
}

// ---------------- fused alpha + gather, iteration 2 ------------------------------
__global__ __launch_bounds__(256) void k_gather2(const int* __restrict__ se,
                                                 const int* __restrict__ bs,
                                                 const int* __restrict__ su,
                                                 const int* __restrict__ sul) {
    __shared__ float4 sbc[8][2][17];
    int t = threadIdx.x, w = t >> 5, l = t & 31, sub = l & 15, half = l >> 4;
    int n = (blockIdx.x * 8 + w) * 2 + half;

    int idx = se[n * KK + sub];
    int e   = bs[n * KK + sub];
    int j   = __ldg(&su[e]);
    float msk = (__ldg(&sul[e]) > 0) ? 1.f : 0.f;
    float v = __ldg(&d_gp1[idx]) + msk * __ldg(&d_gm1[j]);
    v = (v > 0.f) ? v : 0.2f * v;
    float alpha = softmax16((idx == 0) ? NEGINF : v);

    sbc[w][half][sub] = make_float4(alpha, __int_as_float(idx), __int_as_float(j),
                                    alpha * msk);
    __syncwarp();

    float4 accA = make_float4(0.f, 0.f, 0.f, 0.f);
    float4 accB = make_float4(0.f, 0.f, 0.f, 0.f);
    #pragma unroll
    for (int k = 0; k < KK; k++) {
        float4 b = sbc[w][half][k];
        int i  = __float_as_int(b.y);
        int jj = __float_as_int(b.z);
        float4 vv = d_hp1v[i * 16 + sub];
        accA.x += b.x * vv.x; accA.y += b.x * vv.y; accA.z += b.x * vv.z; accA.w += b.x * vv.w;
        float4 u = d_hp1v[jj * 16 + sub];
        accB.x += b.w * u.x; accB.y += b.w * u.y; accB.z += b.w * u.z; accB.w += b.w * u.w;
    }
    d_accAv[n * 16 + sub] = accA;
    d_accBv[n * 16 + sub] = accB;
}

#define FMA4(o, a, w0, w1, w2, w3)                                     \
    o.x += a.x * w0.x + a.y * w1.x + a.z * w2.x + a.w * w3.x;          \
    o.y += a.x * w0.y + a.y * w1.y + a.z * w2.y + a.w * w3.y;          \
    o.z += a.x * w0.z + a.y * w1.z + a.z * w2.z + a.w * w3.z;          \
    o.w += a.x * w0.w + a.y * w1.w + a.z * w2.w + a.w * w3.w;

#define ELU4(o) \
    o.x = (o.x > 0.f) ? o.x : expm1f(o.x); \
    o.y = (o.y > 0.f) ? o.y : expm1f(o.y); \
    o.z = (o.z > 0.f) ? o.z : expm1f(o.z); \
    o.w = (o.w > 0.f) ? o.w : expm1f(o.w);

// ---------------- GEMM, iteration 1 (64 nodes per block) --------------------------
__global__ __launch_bounds__(256) void k_gemm1(const float* __restrict__ Wg) {
    __shared__ float4 sW[HH * 16];
    __shared__ float4 sM[AD * 16];
    __shared__ float  sacc[64][68];
    __shared__ float  sax[64 * 17];
    int t = threadIdx.x;
    int nb0 = blockIdx.x * 64;
    for (int i = t; i < HH * 16; i += 256) sW[i] = ((const float4*)Wg)[i];
    for (int i = t; i < AD * 16; i += 256) sM[i] = d_M14[i];
    for (int i = t; i < 1024; i += 256) {
        int node = i >> 4, s = i & 15, n = nb0 + node;
        float4 v = (n < NN) ? d_accAv[n * 16 + s] : make_float4(0.f, 0.f, 0.f, 0.f);
        *(float4*)&sacc[node][s * 4] = v;
    }
    for (int i = t; i < 1024; i += 256) {
        int node = i >> 4, r = i & 15, n = nb0 + node;
        sax[node * 17 + r] = (n < NN) ? d_accX16[n * 16 + r] : 0.f;
    }
    __syncthreads();

    int ch = t & 15, g = t >> 4;
    int nl = g * 4;
    float4 bm = d_bm4[ch];
    float4 o0 = bm, o1 = bm, o2 = bm, o3 = bm;
    #pragma unroll
    for (int s4 = 0; s4 < 16; s4++) {
        float4 w0 = sW[(4 * s4 + 0) * 16 + ch];
        float4 w1 = sW[(4 * s4 + 1) * 16 + ch];
        float4 w2 = sW[(4 * s4 + 2) * 16 + ch];
        float4 w3 = sW[(4 * s4 + 3) * 16 + ch];
        float4 a0 = *(float4*)&sacc[nl + 0][s4 * 4];
        float4 a1 = *(float4*)&sacc[nl + 1][s4 * 4];
        float4 a2 = *(float4*)&sacc[nl + 2][s4 * 4];
        float4 a3 = *(float4*)&sacc[nl + 3][s4 * 4];
        FMA4(o0, a0, w0, w1, w2, w3)
        FMA4(o1, a1, w0, w1, w2, w3)
        FMA4(o2, a2, w0, w1, w2, w3)
        FMA4(o3, a3, w0, w1, w2, w3)
    }
    #pragma unroll
    for (int rr = 0; rr < AD; rr++) {
        float4 m = sM[rr * 16 + ch];
        float x0 = sax[(nl + 0) * 17 + rr], x1 = sax[(nl + 1) * 17 + rr];
        float x2 = sax[(nl + 2) * 17 + rr], x3 = sax[(nl + 3) * 17 + rr];
        o0.x += x0 * m.x; o0.y += x0 * m.y; o0.z += x0 * m.z; o0.w += x0 * m.w;
        o1.x += x1 * m.x; o1.y += x1 * m.y; o1.z += x1 * m.z; o1.w += x1 * m.w;
        o2.x += x2 * m.x; o2.y += x2 * m.y; o2.z += x2 * m.z; o2.w += x2 * m.w;
        o3.x += x3 * m.x; o3.y += x3 * m.y; o3.z += x3 * m.z; o3.w += x3 * m.w;
    }
    ELU4(o0) ELU4(o1) ELU4(o2) ELU4(o3)

    float4 p = d_p4[ch], q = d_q4[ch];
    float pp0 = o0.x*p.x + o0.y*p.y + o0.z*p.z + o0.w*p.w;
    float pp1 = o1.x*p.x + o1.y*p.y + o1.z*p.z + o1.w*p.w;
    float pp2 = o2.x*p.x + o2.y*p.y + o2.z*p.z + o2.w*p.w;
    float pp3 = o3.x*p.x + o3.y*p.y + o3.z*p.z + o3.w*p.w;
    float qq0 = o0.x*q.x + o0.y*q.y + o0.z*q.z + o0.w*q.w;
    float qq1 = o1.x*q.x + o1.y*q.y + o1.z*q.z + o1.w*q.w;
    float qq2 = o2.x*q.x + o2.y*q.y + o2.z*q.z + o2.w*q.w;
    float qq3 = o3.x*q.x + o3.y*q.y + o3.z*q.z + o3.w*q.w;
    #pragma unroll
    for (int m = 8; m; m >>= 1) {
        pp0 += __shfl_xor_sync(0xffffffffu, pp0, m, 16);
        pp1 += __shfl_xor_sync(0xffffffffu, pp1, m, 16);
        pp2 += __shfl_xor_sync(0xffffffffu, pp2, m, 16);
        pp3 += __shfl_xor_sync(0xffffffffu, pp3, m, 16);
        qq0 += __shfl_xor_sync(0xffffffffu, qq0, m, 16);
        qq1 += __shfl_xor_sync(0xffffffffu, qq1, m, 16);
        qq2 += __shfl_xor_sync(0xffffffffu, qq2, m, 16);
        qq3 += __shfl_xor_sync(0xffffffffu, qq3, m, 16);
    }
    #pragma unroll
    for (int i = 0; i < 4; i++) {
        int n = nb0 + nl + i;
        if (n >= NN) continue;
        int row = n + 1;
        float4 o = (i == 0) ? o0 : (i == 1) ? o1 : (i == 2) ? o2 : o3;
        float pp = (i == 0) ? pp0 : (i == 1) ? pp1 : (i == 2) ? pp2 : pp3;
        float qq = (i == 0) ? qq0 : (i == 1) ? qq1 : (i == 2) ? qq2 : qq3;
        d_hp1v[row * 16 + ch] = o;
        if (ch == 0) { d_gp1[row] = pp; d_gm1[row] = qq; }
    }
    if (blockIdx.x == 0 && t < 16) d_hp1v[t] = make_float4(0.f, 0.f, 0.f, 0.f);
    if (blockIdx.x == 0 && t == 0) { d_gp1[0] = 0.f; d_gm1[0] = 0.f; }
}

// ---------------- GEMM, iteration 2 ------------------------------------------------
__global__ __launch_bounds__(256) void k_gemm2(const float* __restrict__ Wg,
                                               const float* __restrict__ Wm) {
    __shared__ float4 sW[HH * 16];
    __shared__ float  sacc[64][68];
    int t = threadIdx.x;
    int nb0 = blockIdx.x * 64;
    int ch = t & 15, g = t >> 4;
    int nl = g * 4;
    float4 o0 = make_float4(0.f,0.f,0.f,0.f), o1 = o0, o2 = o0, o3 = o0;

    for (int pass = 0; pass < 2; pass++) {
        const float4* W = (pass == 0) ? (const float4*)Wg : (const float4*)Wm;
        const float4* A = (pass == 0) ? d_accAv : d_accBv;
        for (int i = t; i < HH * 16; i += 256) sW[i] = W[i];
        for (int i = t; i < 1024; i += 256) {
            int node = i >> 4, s = i & 15, n = nb0 + node;
            float4 v = (n < NN) ? A[n * 16 + s] : make_float4(0.f, 0.f, 0.f, 0.f);
            *(float4*)&sacc[node][s * 4] = v;
        }
        __syncthreads();
        #pragma unroll
        for (int s4 = 0; s4 < 16; s4++) {
            float4 w0 = sW[(4 * s4 + 0) * 16 + ch];
            float4 w1 = sW[(4 * s4 + 1) * 16 + ch];
            float4 w2 = sW[(4 * s4 + 2) * 16 + ch];
            float4 w3 = sW[(4 * s4 + 3) * 16 + ch];
            float4 a0 = *(float4*)&sacc[nl + 0][s4 * 4];
            float4 a1 = *(float4*)&sacc[nl + 1][s4 * 4];
            float4 a2 = *(float4*)&sacc[nl + 2][s4 * 4];
            float4 a3 = *(float4*)&sacc[nl + 3][s4 * 4];
            FMA4(o0, a0, w0, w1, w2, w3)
            FMA4(o1, a1, w0, w1, w2, w3)
            FMA4(o2, a2, w0, w1, w2, w3)
            FMA4(o3, a3, w0, w1, w2, w3)
        }
        __syncthreads();
    }
    ELU4(o0) ELU4(o1) ELU4(o2) ELU4(o3)
    #pragma unroll
    for (int i = 0; i < 4; i++) {
        int n = nb0 + nl + i;
        if (n >= NN) continue;
        float4 o = (i == 0) ? o0 : (i == 1) ? o1 : (i == 2) ? o2 : o3;
        d_hp2v[(n + 1) * 16 + ch] = o;
    }
    if (blockIdx.x == 0 && t < 16) d_hp2v[t] = make_float4(0.f, 0.f, 0.f, 0.f);
}

// ---------------- readout ----------------------------------------------------------
__global__ __launch_bounds__(256) void k_out(const int* __restrict__ ls,
                                             float* __restrict__ out) {
    int wid = (blockIdx.x * blockDim.x + threadIdx.x) >> 5;
    int l = threadIdx.x & 31;
    int sub = l & 15;
    int mol = wid * 2 + (l >> 4);
    if (mol >= BBATCH) return;
    const int* row = ls + mol * MAXM;
    float4 acc = make_float4(0.f, 0.f, 0.f, 0.f);
    #pragma unroll 8
    for (int m = 0; m < MAXM; m++) {
        int i = __ldg(row + m);
        float4 v = d_hp2v[i * 16 + sub];
        acc.x += v.x; acc.y += v.y; acc.z += v.z; acc.w += v.w;
    }
    ((float4*)out)[mol * 16 + sub] = acc;
}

// ---------------- launch -----------------------------------------------------------
extern "C" void kernel_launch(void* const* d_in, const int* in_sizes, int n_in,
                              void* d_out, int out_size) {
    const float* tf  = (const float*)d_in[0];
    const float* fdg = (const float*)d_in[1];
    const float* rij = (const float*)d_in[2];
    const int*   se  = (const int*)d_in[3];
    const int*   bs  = (const int*)d_in[4];
    const int*   ls  = (const int*)d_in[5];
    const int*   su  = (const int*)d_in[6];
    const int*   sul = (const int*)d_in[7];
    const float* We  = (const float*)d_in[8];
    const float* be  = (const float*)d_in[9];
    const float* Wd  = (const float*)d_in[10];
    const float* bd  = (const float*)d_in[11];
    const float* Wg  = (const float*)d_in[12];
    const float* Wm  = (const float*)d_in[13];
    const float* ag  = (const float*)d_in[14];

    int gat_blocks = NN / 16;               // 3125
    int gemm_blocks = (NN + 63) / 64;       // 782

    k_consts<<<1, 256>>>(Wg, Wm, ag, Wd, bd, We, be);
    k_pre<<<NB_EMB + NB_ELOG, 256>>>(tf, We, be, fdg, rij);

    k_gather1<<<gat_blocks, 256>>>(se, bs, fdg, rij);
    k_gemm1<<<gemm_blocks, 256>>>(Wg);

    k_gather2<<<gat_blocks, 256>>>(se, bs, su, sul);
    k_gemm2<<<gemm_blocks, 256>>>(Wg, Wm);

    k_out<<<(BBATCH / 2 + 7) / 8, 256>>>(ls, (float*)d_out);
}

// round 6
// speedup vs baseline: 2.4219x; 1.0628x over previous
#include <cuda_runtime.h>
#include <math.h>

#define NN 50000
#define KK 16
#define EE 800000
#define BBATCH 1024
#define MAXM 48
#define FD 9
#define AD 10
#define HH 64
#define NEGINF (-1e9f)
#define NB_EMB 3126              // ceil((NN+1)/16)
#define NB_ELOG 3125             // EE/256

// ---------------- scratch ------------------------------------------------------
__device__ float4 d_hp0v[(NN + 1) * 16];
__device__ float4 d_th1v[(NN + 1) * 16];   // hp1 @ Wg (row 0 = 0)
__device__ float4 d_tm1v[(NN + 1) * 16];   // hp1 @ Wm (row 0 = 0)
__device__ float4 d_hp2v[(NN + 1) * 16];
__device__ float d_gp0[NN + 1];
__device__ float d_gp1[NN + 1];
__device__ float d_gm1[NN + 1];
__device__ float d_elog[EE];
__device__ float4 d_accAv[NN * 16];
__device__ float d_accX16[NN * 16];
__device__ float4 d_p4[16];
__device__ float4 d_q4[16];
__device__ float d_qd[AD];
__device__ float d_c;
__device__ float d_wep[FD];      // We @ p
__device__ float d_c0;           // be . p
__device__ float4 d_M14[AD * 16];
__device__ float4 d_bm4[16];

// ---------------- constants -----------------------------------------------------
__global__ __launch_bounds__(256) void k_consts(const float* __restrict__ Wg,
                                                const float* __restrict__ Wm,
                                                const float* __restrict__ a,
                                                const float* __restrict__ Wd,
                                                const float* __restrict__ bd,
                                                const float* __restrict__ We,
                                                const float* __restrict__ be) {
    __shared__ float sp[HH], sq[HH];
    int t = threadIdx.x;
    if (t < HH) {
        float p = 0.f, q = 0.f;
        #pragma unroll 8
        for (int i = 0; i < HH; i++) {
            p += Wg[t * HH + i] * a[i];
            q += Wm[t * HH + i] * a[HH + i];
        }
        sp[t] = p; sq[t] = q;
        ((float*)d_p4)[t] = p;
        ((float*)d_q4)[t] = q;
    }
    __syncthreads();
    if (t < AD) {
        float s = 0.f;
        for (int i = 0; i < HH; i++) s += Wd[t * HH + i] * sq[i];
        d_qd[t] = s;
    } else if (t == AD) {
        float s = 0.f;
        for (int i = 0; i < HH; i++) s += bd[i] * sq[i];
        d_c = s;
    } else if (t >= 32 && t < 32 + FD) {
        int r = t - 32;
        float s = 0.f;
        for (int j = 0; j < HH; j++) s += We[r * HH + j] * sp[j];
        d_wep[r] = s;
    } else if (t == 32 + FD) {
        float s = 0.f;
        for (int j = 0; j < HH; j++) s += be[j] * sp[j];
        d_c0 = s;
    }
    for (int idx = t; idx < AD * HH; idx += 256) {
        int r = idx >> 6, j = idx & 63;
        float s = 0.f;
        #pragma unroll 8
        for (int i = 0; i < HH; i++) s += Wd[r * HH + i] * Wm[i * HH + j];
        ((float*)d_M14)[idx] = s;
    }
    if (t < HH) {
        float s = 0.f;
        for (int i = 0; i < HH; i++) s += bd[i] * Wm[i * HH + t];
        ((float*)d_bm4)[t] = s;
    }
}

// ---------------- fused embed (+gp0) and per-edge logit --------------------------
__global__ __launch_bounds__(256) void k_pre(const float* __restrict__ tf,
                                             const float* __restrict__ We,
                                             const float* __restrict__ be,
                                             const float* __restrict__ fdg,
                                             const float* __restrict__ rij) {
    int b = blockIdx.x;
    if (b < NB_EMB) {
        int t = threadIdx.x, w = t >> 5, l = t & 31, sub = l & 15, half = l >> 4;
        int row = b * 16 + w * 2 + half;
        if (row > NN) return;
        float4 acc = make_float4(0.f, 0.f, 0.f, 0.f);
        float g = 0.f;
        if (row > 0) {
            int n = row - 1;
            const float* r = tf + n * FD;
            acc = ((const float4*)be)[sub];
            g = d_c0;
            #pragma unroll
            for (int tt = 0; tt < FD; tt++) {
                float x = __ldg(r + tt);
                float4 ww = ((const float4*)We)[tt * 16 + sub];
                acc.x += x * ww.x; acc.y += x * ww.y; acc.z += x * ww.z; acc.w += x * ww.w;
                g += x * d_wep[tt];
            }
        }
        d_hp0v[row * 16 + sub] = acc;
        if (sub == 0) d_gp0[row] = g;
    } else {
        int e = (b - NB_EMB) * 256 + threadIdx.x;
        if (e >= EE) return;
        float s = d_c + rij[e] * d_qd[9];
        const float* x = fdg + (long)e * FD;
        #pragma unroll
        for (int r = 0; r < FD; r++) s += x[r] * d_qd[r];
        d_elog[e] = s;
    }
}

// ---------------- softmax helper (width 16) --------------------------------------
__device__ __forceinline__ float softmax16(float logit) {
    float mx = logit;
    #pragma unroll
    for (int m = 8; m; m >>= 1) mx = fmaxf(mx, __shfl_xor_sync(0xffffffffu, mx, m, 16));
    float ex = __expf(logit - mx);
    float sum = ex;
    #pragma unroll
    for (int m = 8; m; m >>= 1) sum += __shfl_xor_sync(0xffffffffu, sum, m, 16);
    return ex / sum;
}

// ---------------- fused alpha + gather, iteration 1 ------------------------------
__global__ __launch_bounds__(256) void k_gather1(const int* __restrict__ se,
                                                 const int* __restrict__ bs,
                                                 const float* __restrict__ fdg,
                                                 const float* __restrict__ rij) {
    __shared__ float4 sbc[8][2][17];
    int t = threadIdx.x, w = t >> 5, l = t & 31, sub = l & 15, half = l >> 4;
    int n = (blockIdx.x * 8 + w) * 2 + half;     // < NN exactly

    int idx = se[n * KK + sub];
    int e   = bs[n * KK + sub];
    float v = __ldg(&d_gp0[idx]) + __ldg(&d_elog[e]);
    v = (v > 0.f) ? v : 0.2f * v;
    float alpha = softmax16((idx == 0) ? NEGINF : v);

    sbc[w][half][sub] = make_float4(alpha, __int_as_float(idx), __int_as_float(e), 0.f);
    __syncwarp();

    float4 acc = make_float4(0.f, 0.f, 0.f, 0.f);
    float ax = 0.f;
    #pragma unroll
    for (int k = 0; k < KK; k++) {
        float4 b = sbc[w][half][k];
        int i  = __float_as_int(b.y);
        int ee = __float_as_int(b.z);
        float4 vv = d_hp0v[i * 16 + sub];
        acc.x += b.x * vv.x; acc.y += b.x * vv.y; acc.z += b.x * vv.z; acc.w += b.x * vv.w;
        if (sub < AD) {
            float x = (sub < FD) ? fdg[(long)ee * FD + sub] : rij[ee];
            ax += b.x * x;
        }
    }
    d_accAv[n * 16 + sub] = acc;
    d_accX16[n * 16 + sub] = ax;
}

#define FMA4(o, a, w0, w1, w2, w3)                                     \
    o.x += a.x * w0.x + a.y * w1.x + a.z * w2.x + a.w * w3.x;          \
    o.y += a.x * w0.y + a.y * w1.y + a.z * w2.y + a.w * w3.y;          \
    o.z += a.x * w0.z + a.y * w1.z + a.z * w2.z + a.w * w3.z;          \
    o.w += a.x * w0.w + a.y * w1.w + a.z * w2.w + a.w * w3.w;

#define ELU4(o) \
    o.x = (o.x > 0.f) ? o.x : expm1f(o.x); \
    o.y = (o.y > 0.f) ? o.y : expm1f(o.y); \
    o.z = (o.z > 0.f) ? o.z : expm1f(o.z); \
    o.w = (o.w > 0.f) ? o.w : expm1f(o.w);

// ---------------- mega GEMM: hp1 = ELU(accA@Wg + accX@M1 + bm);
//                  th1 = hp1@Wg; tm1 = hp1@Wm; gp1/gm1 scalars --------------------
__global__ __launch_bounds__(256) void k_mega(const float* __restrict__ Wg,
                                              const float* __restrict__ Wm) {
    extern __shared__ float4 dyn[];
    float4* sW  = dyn;                        // 1024 f4 = 16 KB (Wg, then Wm)
    float4* sM  = dyn + 1024;                 // 160 f4 = 2.5 KB
    float*  sacc = (float*)(dyn + 1184);      // 64*68 = 17.4 KB
    float*  sax  = sacc + 64 * 68;            // 64*17 = 4.3 KB
    float*  shp  = sax + 64 * 17;             // 64*68 = 17.4 KB

    int t = threadIdx.x;
    int nb0 = blockIdx.x * 64;
    for (int i = t; i < HH * 16; i += 256) sW[i] = ((const float4*)Wg)[i];
    for (int i = t; i < AD * 16; i += 256) sM[i] = d_M14[i];
    for (int i = t; i < 1024; i += 256) {
        int node = i >> 4, s = i & 15, n = nb0 + node;
        float4 v = (n < NN) ? d_accAv[n * 16 + s] : make_float4(0.f, 0.f, 0.f, 0.f);
        *(float4*)&sacc[node * 68 + s * 4] = v;
    }
    for (int i = t; i < 1024; i += 256) {
        int node = i >> 4, r = i & 15, n = nb0 + node;
        sax[node * 17 + r] = (n < NN) ? d_accX16[n * 16 + r] : 0.f;
    }
    __syncthreads();

    int ch = t & 15, g = t >> 4;
    int nl = g * 4;

    // ---- pass 1: hp1 = ELU(accA@Wg + accX@M1 + bm) ----
    float4 bm = d_bm4[ch];
    float4 o0 = bm, o1 = bm, o2 = bm, o3 = bm;
    #pragma unroll
    for (int s4 = 0; s4 < 16; s4++) {
        float4 w0 = sW[(4 * s4 + 0) * 16 + ch];
        float4 w1 = sW[(4 * s4 + 1) * 16 + ch];
        float4 w2 = sW[(4 * s4 + 2) * 16 + ch];
        float4 w3 = sW[(4 * s4 + 3) * 16 + ch];
        float4 a0 = *(float4*)&sacc[(nl + 0) * 68 + s4 * 4];
        float4 a1 = *(float4*)&sacc[(nl + 1) * 68 + s4 * 4];
        float4 a2 = *(float4*)&sacc[(nl + 2) * 68 + s4 * 4];
        float4 a3 = *(float4*)&sacc[(nl + 3) * 68 + s4 * 4];
        FMA4(o0, a0, w0, w1, w2, w3)
        FMA4(o1, a1, w0, w1, w2, w3)
        FMA4(o2, a2, w0, w1, w2, w3)
        FMA4(o3, a3, w0, w1, w2, w3)
    }
    #pragma unroll
    for (int rr = 0; rr < AD; rr++) {
        float4 m = sM[rr * 16 + ch];
        float x0 = sax[(nl + 0) * 17 + rr], x1 = sax[(nl + 1) * 17 + rr];
        float x2 = sax[(nl + 2) * 17 + rr], x3 = sax[(nl + 3) * 17 + rr];
        o0.x += x0 * m.x; o0.y += x0 * m.y; o0.z += x0 * m.z; o0.w += x0 * m.w;
        o1.x += x1 * m.x; o1.y += x1 * m.y; o1.z += x1 * m.z; o1.w += x1 * m.w;
        o2.x += x2 * m.x; o2.y += x2 * m.y; o2.z += x2 * m.z; o2.w += x2 * m.w;
        o3.x += x3 * m.x; o3.y += x3 * m.y; o3.z += x3 * m.z; o3.w += x3 * m.w;
    }
    ELU4(o0) ELU4(o1) ELU4(o2) ELU4(o3)

    // gp1/gm1 scalars
    {
        float4 p = d_p4[ch], q = d_q4[ch];
        float pp0 = o0.x*p.x + o0.y*p.y + o0.z*p.z + o0.w*p.w;
        float pp1 = o1.x*p.x + o1.y*p.y + o1.z*p.z + o1.w*p.w;
        float pp2 = o2.x*p.x + o2.y*p.y + o2.z*p.z + o2.w*p.w;
        float pp3 = o3.x*p.x + o3.y*p.y + o3.z*p.z + o3.w*p.w;
        float qq0 = o0.x*q.x + o0.y*q.y + o0.z*q.z + o0.w*q.w;
        float qq1 = o1.x*q.x + o1.y*q.y + o1.z*q.z + o1.w*q.w;
        float qq2 = o2.x*q.x + o2.y*q.y + o2.z*q.z + o2.w*q.w;
        float qq3 = o3.x*q.x + o3.y*q.y + o3.z*q.z + o3.w*q.w;
        #pragma unroll
        for (int m = 8; m; m >>= 1) {
            pp0 += __shfl_xor_sync(0xffffffffu, pp0, m, 16);
            pp1 += __shfl_xor_sync(0xffffffffu, pp1, m, 16);
            pp2 += __shfl_xor_sync(0xffffffffu, pp2, m, 16);
            pp3 += __shfl_xor_sync(0xffffffffu, pp3, m, 16);
            qq0 += __shfl_xor_sync(0xffffffffu, qq0, m, 16);
            qq1 += __shfl_xor_sync(0xffffffffu, qq1, m, 16);
            qq2 += __shfl_xor_sync(0xffffffffu, qq2, m, 16);
            qq3 += __shfl_xor_sync(0xffffffffu, qq3, m, 16);
        }
        if (ch == 0) {
            if (nb0 + nl + 0 < NN) { d_gp1[nb0 + nl + 1] = pp0; d_gm1[nb0 + nl + 1] = qq0; }
            if (nb0 + nl + 1 < NN) { d_gp1[nb0 + nl + 2] = pp1; d_gm1[nb0 + nl + 2] = qq1; }
            if (nb0 + nl + 2 < NN) { d_gp1[nb0 + nl + 3] = pp2; d_gm1[nb0 + nl + 3] = qq2; }
            if (nb0 + nl + 3 < NN) { d_gp1[nb0 + nl + 4] = pp3; d_gm1[nb0 + nl + 4] = qq3; }
        }
    }

    // stash hp1 into shared for passes 2/3
    *(float4*)&shp[(nl + 0) * 68 + ch * 4] = o0;
    *(float4*)&shp[(nl + 1) * 68 + ch * 4] = o1;
    *(float4*)&shp[(nl + 2) * 68 + ch * 4] = o2;
    *(float4*)&shp[(nl + 3) * 68 + ch * 4] = o3;
    __syncthreads();

    // ---- pass 2: th1 = hp1 @ Wg (sW already holds Wg) ----
    float4 u0 = make_float4(0.f,0.f,0.f,0.f), u1 = u0, u2 = u0, u3 = u0;
    #pragma unroll
    for (int s4 = 0; s4 < 16; s4++) {
        float4 w0 = sW[(4 * s4 + 0) * 16 + ch];
        float4 w1 = sW[(4 * s4 + 1) * 16 + ch];
        float4 w2 = sW[(4 * s4 + 2) * 16 + ch];
        float4 w3 = sW[(4 * s4 + 3) * 16 + ch];
        float4 a0 = *(float4*)&shp[(nl + 0) * 68 + s4 * 4];
        float4 a1 = *(float4*)&shp[(nl + 1) * 68 + s4 * 4];
        float4 a2 = *(float4*)&shp[(nl + 2) * 68 + s4 * 4];
        float4 a3 = *(float4*)&shp[(nl + 3) * 68 + s4 * 4];
        FMA4(u0, a0, w0, w1, w2, w3)
        FMA4(u1, a1, w0, w1, w2, w3)
        FMA4(u2, a2, w0, w1, w2, w3)
        FMA4(u3, a3, w0, w1, w2, w3)
    }
    if (nb0 + nl + 0 < NN) d_th1v[(nb0 + nl + 1) * 16 + ch] = u0;
    if (nb0 + nl + 1 < NN) d_th1v[(nb0 + nl + 2) * 16 + ch] = u1;
    if (nb0 + nl + 2 < NN) d_th1v[(nb0 + nl + 3) * 16 + ch] = u2;
    if (nb0 + nl + 3 < NN) d_th1v[(nb0 + nl + 4) * 16 + ch] = u3;
    __syncthreads();

    // ---- pass 3: tm1 = hp1 @ Wm (reload sW) ----
    for (int i = t; i < HH * 16; i += 256) sW[i] = ((const float4*)Wm)[i];
    __syncthreads();
    u0 = make_float4(0.f,0.f,0.f,0.f); u1 = u0; u2 = u0; u3 = u0;
    #pragma unroll
    for (int s4 = 0; s4 < 16; s4++) {
        float4 w0 = sW[(4 * s4 + 0) * 16 + ch];
        float4 w1 = sW[(4 * s4 + 1) * 16 + ch];
        float4 w2 = sW[(4 * s4 + 2) * 16 + ch];
        float4 w3 = sW[(4 * s4 + 3) * 16 + ch];
        float4 a0 = *(float4*)&shp[(nl + 0) * 68 + s4 * 4];
        float4 a1 = *(float4*)&shp[(nl + 1) * 68 + s4 * 4];
        float4 a2 = *(float4*)&shp[(nl + 2) * 68 + s4 * 4];
        float4 a3 = *(float4*)&shp[(nl + 3) * 68 + s4 * 4];
        FMA4(u0, a0, w0, w1, w2, w3)
        FMA4(u1, a1, w0, w1, w2, w3)
        FMA4(u2, a2, w0, w1, w2, w3)
        FMA4(u3, a3, w0, w1, w2, w3)
    }
    if (nb0 + nl + 0 < NN) d_tm1v[(nb0 + nl + 1) * 16 + ch] = u0;
    if (nb0 + nl + 1 < NN) d_tm1v[(nb0 + nl + 2) * 16 + ch] = u1;
    if (nb0 + nl + 2 < NN) d_tm1v[(nb0 + nl + 3) * 16 + ch] = u2;
    if (nb0 + nl + 3 < NN) d_tm1v[(nb0 + nl + 4) * 16 + ch] = u3;

    // pad rows
    if (blockIdx.x == 0 && t < 16) {
        d_th1v[t] = make_float4(0.f, 0.f, 0.f, 0.f);
        d_tm1v[t] = make_float4(0.f, 0.f, 0.f, 0.f);
    }
    if (blockIdx.x == 0 && t == 0) { d_gp1[0] = 0.f; d_gm1[0] = 0.f; }
}

// ---------------- fused alpha + gather + ELU, iteration 2 (final) ----------------
__global__ __launch_bounds__(256) void k_gather2(const int* __restrict__ se,
                                                 const int* __restrict__ bs,
                                                 const int* __restrict__ su,
                                                 const int* __restrict__ sul) {
    __shared__ float4 sbc[8][2][17];
    int t = threadIdx.x, w = t >> 5, l = t & 31, sub = l & 15, half = l >> 4;
    int n = (blockIdx.x * 8 + w) * 2 + half;

    int idx = se[n * KK + sub];
    int e   = bs[n * KK + sub];
    int j   = __ldg(&su[e]);
    float msk = (__ldg(&sul[e]) > 0) ? 1.f : 0.f;
    float v = __ldg(&d_gp1[idx]) + msk * __ldg(&d_gm1[j]);
    v = (v > 0.f) ? v : 0.2f * v;
    float alpha = softmax16((idx == 0) ? NEGINF : v);

    sbc[w][half][sub] = make_float4(alpha, __int_as_float(idx), __int_as_float(j),
                                    alpha * msk);
    __syncwarp();

    float4 acc = make_float4(0.f, 0.f, 0.f, 0.f);
    #pragma unroll
    for (int k = 0; k < KK; k++) {
        float4 b = sbc[w][half][k];
        int i  = __float_as_int(b.y);
        int jj = __float_as_int(b.z);
        float4 vv = d_th1v[i * 16 + sub];
        acc.x += b.x * vv.x; acc.y += b.x * vv.y; acc.z += b.x * vv.z; acc.w += b.x * vv.w;
        float4 u = d_tm1v[jj * 16 + sub];
        acc.x += b.w * u.x; acc.y += b.w * u.y; acc.z += b.w * u.z; acc.w += b.w * u.w;
    }
    ELU4(acc)
    d_hp2v[(n + 1) * 16 + sub] = acc;
    if (blockIdx.x == 0 && t < 16) d_hp2v[t] = make_float4(0.f, 0.f, 0.f, 0.f);
}

// ---------------- readout ----------------------------------------------------------
__global__ __launch_bounds__(256) void k_out(const int* __restrict__ ls,
                                             float* __restrict__ out) {
    int wid = (blockIdx.x * blockDim.x + threadIdx.x) >> 5;
    int l = threadIdx.x & 31;
    int sub = l & 15;
    int mol = wid * 2 + (l >> 4);
    if (mol >= BBATCH) return;
    const int* row = ls + mol * MAXM;
    float4 acc = make_float4(0.f, 0.f, 0.f, 0.f);
    #pragma unroll 8
    for (int m = 0; m < MAXM; m++) {
        int i = __ldg(row + m);
        float4 v = d_hp2v[i * 16 + sub];
        acc.x += v.x; acc.y += v.y; acc.z += v.z; acc.w += v.w;
    }
    ((float4*)out)[mol * 16 + sub] = acc;
}

// ---------------- launch -----------------------------------------------------------
extern "C" void kernel_launch(void* const* d_in, const int* in_sizes, int n_in,
                              void* d_out, int out_size) {
    const float* tf  = (const float*)d_in[0];
    const float* fdg = (const float*)d_in[1];
    const float* rij = (const float*)d_in[2];
    const int*   se  = (const int*)d_in[3];
    const int*   bs  = (const int*)d_in[4];
    const int*   ls  = (const int*)d_in[5];
    const int*   su  = (const int*)d_in[6];
    const int*   sul = (const int*)d_in[7];
    const float* We  = (const float*)d_in[8];
    const float* be  = (const float*)d_in[9];
    const float* Wd  = (const float*)d_in[10];
    const float* bd  = (const float*)d_in[11];
    const float* Wg  = (const float*)d_in[12];
    const float* Wm  = (const float*)d_in[13];
    const float* ag  = (const float*)d_in[14];

    // dyn smem: sW 16K + sM 2.5K + sacc 17.4K + sax 4.3K + shp 17.4K
    int mega_smem = (1184 * 16) + 64 * 68 * 4 + 64 * 17 * 4 + 64 * 68 * 4;  // 58112
    static int smem_set = 0;
    if (!smem_set) {
        cudaFuncSetAttribute(k_mega, cudaFuncAttributeMaxDynamicSharedMemorySize, mega_smem);
        smem_set = 1;
    }

    int gat_blocks = NN / 16;               // 3125
    int gemm_blocks = (NN + 63) / 64;       // 782

    k_consts<<<1, 256>>>(Wg, Wm, ag, Wd, bd, We, be);
    k_pre<<<NB_EMB + NB_ELOG, 256>>>(tf, We, be, fdg, rij);

    k_gather1<<<gat_blocks, 256>>>(se, bs, fdg, rij);
    k_mega<<<gemm_blocks, 256, mega_smem>>>(Wg, Wm);
    k_gather2<<<gat_blocks, 256>>>(se, bs, su, sul);

    k_out<<<(BBATCH / 2 + 7) / 8, 256>>>(ls, (float*)d_out);
}

// round 7
// speedup vs baseline: 2.4223x; 1.0002x over previous
#include <cuda_runtime.h>
#include <math.h>

#define NN 50000
#define KK 16
#define EE 800000
#define BBATCH 1024
#define MAXM 48
#define FD 9
#define AD 10
#define HH 64
#define NEGINF (-1e9f)
#define NB_EMB 3126              // ceil((NN+1)/16)
#define NB_ELOG 3125             // EE/256

// ---------------- scratch ------------------------------------------------------
__device__ float4 d_hp0v[(NN + 1) * 16];
__device__ float4 d_th1v[(NN + 1) * 16];   // hp1 @ Wg (row 0 = 0)
__device__ float4 d_tm1v[(NN + 1) * 16];   // hp1 @ Wm (row 0 = 0)
__device__ float4 d_hp2v[(NN + 1) * 16];
__device__ float d_gp0[NN + 1];
__device__ float d_gp1[NN + 1];
__device__ float d_gm1[NN + 1];
__device__ float d_elog[EE];
__device__ float4 d_accAv[NN * 16];
__device__ float d_accX16[NN * 16];
__device__ float4 d_p4[16];
__device__ float4 d_q4[16];
__device__ float d_qd[AD];
__device__ float d_c;
__device__ float d_wep[FD];      // We @ p
__device__ float d_c0;           // be . p
__device__ float4 d_M14[AD * 16];
__device__ float4 d_bm4[16];

// ---------------- constants -----------------------------------------------------
__global__ __launch_bounds__(256) void k_consts(const float* __restrict__ Wg,
                                                const float* __restrict__ Wm,
                                                const float* __restrict__ a,
                                                const float* __restrict__ Wd,
                                                const float* __restrict__ bd,
                                                const float* __restrict__ We,
                                                const float* __restrict__ be) {
    __shared__ float sp[HH], sq[HH];
    int t = threadIdx.x;
    if (t < HH) {
        float p = 0.f, q = 0.f;
        #pragma unroll 8
        for (int i = 0; i < HH; i++) {
            p += Wg[t * HH + i] * a[i];
            q += Wm[t * HH + i] * a[HH + i];
        }
        sp[t] = p; sq[t] = q;
        ((float*)d_p4)[t] = p;
        ((float*)d_q4)[t] = q;
    }
    __syncthreads();
    if (t < AD) {
        float s = 0.f;
        for (int i = 0; i < HH; i++) s += Wd[t * HH + i] * sq[i];
        d_qd[t] = s;
    } else if (t == AD) {
        float s = 0.f;
        for (int i = 0; i < HH; i++) s += bd[i] * sq[i];
        d_c = s;
    } else if (t >= 32 && t < 32 + FD) {
        int r = t - 32;
        float s = 0.f;
        for (int j = 0; j < HH; j++) s += We[r * HH + j] * sp[j];
        d_wep[r] = s;
    } else if (t == 32 + FD) {
        float s = 0.f;
        for (int j = 0; j < HH; j++) s += be[j] * sp[j];
        d_c0 = s;
    }
    for (int idx = t; idx < AD * HH; idx += 256) {
        int r = idx >> 6, j = idx & 63;
        float s = 0.f;
        #pragma unroll 8
        for (int i = 0; i < HH; i++) s += Wd[r * HH + i] * Wm[i * HH + j];
        ((float*)d_M14)[idx] = s;
    }
    if (t < HH) {
        float s = 0.f;
        for (int i = 0; i < HH; i++) s += bd[i] * Wm[i * HH + t];
        ((float*)d_bm4)[t] = s;
    }
}

// ---------------- fused embed (+gp0) and per-edge logit --------------------------
__global__ __launch_bounds__(256) void k_pre(const float* __restrict__ tf,
                                             const float* __restrict__ We,
                                             const float* __restrict__ be,
                                             const float* __restrict__ fdg,
                                             const float* __restrict__ rij) {
    int b = blockIdx.x;
    if (b < NB_EMB) {
        int t = threadIdx.x, w = t >> 5, l = t & 31, sub = l & 15, half = l >> 4;
        int row = b * 16 + w * 2 + half;
        if (row > NN) return;
        float4 acc = make_float4(0.f, 0.f, 0.f, 0.f);
        float g = 0.f;
        if (row > 0) {
            int n = row - 1;
            const float* r = tf + n * FD;
            acc = ((const float4*)be)[sub];
            g = d_c0;
            #pragma unroll
            for (int tt = 0; tt < FD; tt++) {
                float x = __ldg(r + tt);
                float4 ww = ((const float4*)We)[tt * 16 + sub];
                acc.x += x * ww.x; acc.y += x * ww.y; acc.z += x * ww.z; acc.w += x * ww.w;
                g += x * d_wep[tt];
            }
        }
        d_hp0v[row * 16 + sub] = acc;
        if (sub == 0) d_gp0[row] = g;
    } else {
        int e = (b - NB_EMB) * 256 + threadIdx.x;
        if (e >= EE) return;
        float s = d_c + rij[e] * d_qd[9];
        const float* x = fdg + (long)e * FD;
        #pragma unroll
        for (int r = 0; r < FD; r++) s += x[r] * d_qd[r];
        d_elog[e] = s;
    }
}

// ---------------- softmax helper (width 16) --------------------------------------
__device__ __forceinline__ float softmax16(float logit) {
    float mx = logit;
    #pragma unroll
    for (int m = 8; m; m >>= 1) mx = fmaxf(mx, __shfl_xor_sync(0xffffffffu, mx, m, 16));
    float ex = __expf(logit - mx);
    float sum = ex;
    #pragma unroll
    for (int m = 8; m; m >>= 1) sum += __shfl_xor_sync(0xffffffffu, sum, m, 16);
    return ex / sum;
}

// ---------------- fused alpha + gather, iteration 1 ------------------------------
__global__ __launch_bounds__(256) void k_gather1(const int* __restrict__ se,
                                                 const int* __restrict__ bs,
                                                 const float* __restrict__ fdg,
                                                 const float* __restrict__ rij) {
    __shared__ float4 sbc[8][2][17];
    int t = threadIdx.x, w = t >> 5, l = t & 31, sub = l & 15, half = l >> 4;
    int n = (blockIdx.x * 8 + w) * 2 + half;     // < NN exactly

    int idx = se[n * KK + sub];
    int e   = bs[n * KK + sub];
    float v = __ldg(&d_gp0[idx]) + __ldg(&d_elog[e]);
    v = (v > 0.f) ? v : 0.2f * v;
    float alpha = softmax16((idx == 0) ? NEGINF : v);

    sbc[w][half][sub] = make_float4(alpha, __int_as_float(idx), __int_as_float(e), 0.f);
    __syncwarp();

    float4 acc = make_float4(0.f, 0.f, 0.f, 0.f);
    float ax = 0.f;
    #pragma unroll
    for (int k = 0; k < KK; k++) {
        float4 b = sbc[w][half][k];
        int i  = __float_as_int(b.y);
        int ee = __float_as_int(b.z);
        float4 vv = d_hp0v[i * 16 + sub];
        acc.x += b.x * vv.x; acc.y += b.x * vv.y; acc.z += b.x * vv.z; acc.w += b.x * vv.w;
        if (sub < AD) {
            float x = (sub < FD) ? fdg[(long)ee * FD + sub] : rij[ee];
            ax += b.x * x;
        }
    }
    d_accAv[n * 16 + sub] = acc;
    d_accX16[n * 16 + sub] = ax;
}

#define FMA4(o, a, w0, w1, w2, w3)                                     \
    o.x += a.x * w0.x + a.y * w1.x + a.z * w2.x + a.w * w3.x;          \
    o.y += a.x * w0.y + a.y * w1.y + a.z * w2.y + a.w * w3.y;          \
    o.z += a.x * w0.z + a.y * w1.z + a.z * w2.z + a.w * w3.z;          \
    o.w += a.x * w0.w + a.y * w1.w + a.z * w2.w + a.w * w3.w;

#define ELU4(o) \
    o.x = (o.x > 0.f) ? o.x : expm1f(o.x); \
    o.y = (o.y > 0.f) ? o.y : expm1f(o.y); \
    o.z = (o.z > 0.f) ? o.z : expm1f(o.z); \
    o.w = (o.w > 0.f) ? o.w : expm1f(o.w);

// ---------------- mega GEMM: hp1 = ELU(accA@Wg + accX@M1 + bm);
//                  th1 = hp1@Wg; tm1 = hp1@Wm; gp1/gm1 scalars --------------------
// smem: 16K(sW) + 2.5K(sM) + 17.4K(sacc, reused for hp1) + 4.3K(sax) = 40.2 KB
__global__ __launch_bounds__(256, 4) void k_mega(const float* __restrict__ Wg,
                                                 const float* __restrict__ Wm) {
    __shared__ float4 sW[HH * 16];
    __shared__ float4 sM[AD * 16];
    __shared__ float  sacc[64 * 68];
    __shared__ float  sax[64 * 17];

    int t = threadIdx.x;
    int nb0 = blockIdx.x * 64;
    for (int i = t; i < HH * 16; i += 256) sW[i] = ((const float4*)Wg)[i];
    for (int i = t; i < AD * 16; i += 256) sM[i] = d_M14[i];
    for (int i = t; i < 1024; i += 256) {
        int node = i >> 4, s = i & 15, n = nb0 + node;
        float4 v = (n < NN) ? d_accAv[n * 16 + s] : make_float4(0.f, 0.f, 0.f, 0.f);
        *(float4*)&sacc[node * 68 + s * 4] = v;
    }
    for (int i = t; i < 1024; i += 256) {
        int node = i >> 4, r = i & 15, n = nb0 + node;
        sax[node * 17 + r] = (n < NN) ? d_accX16[n * 16 + r] : 0.f;
    }
    __syncthreads();

    int ch = t & 15, g = t >> 4;
    int nl = g * 4;

    // ---- pass 1: hp1 = ELU(accA@Wg + accX@M1 + bm) ----
    float4 bm = d_bm4[ch];
    float4 o0 = bm, o1 = bm, o2 = bm, o3 = bm;
    #pragma unroll
    for (int s4 = 0; s4 < 16; s4++) {
        float4 w0 = sW[(4 * s4 + 0) * 16 + ch];
        float4 w1 = sW[(4 * s4 + 1) * 16 + ch];
        float4 w2 = sW[(4 * s4 + 2) * 16 + ch];
        float4 w3 = sW[(4 * s4 + 3) * 16 + ch];
        float4 a0 = *(float4*)&sacc[(nl + 0) * 68 + s4 * 4];
        float4 a1 = *(float4*)&sacc[(nl + 1) * 68 + s4 * 4];
        float4 a2 = *(float4*)&sacc[(nl + 2) * 68 + s4 * 4];
        float4 a3 = *(float4*)&sacc[(nl + 3) * 68 + s4 * 4];
        FMA4(o0, a0, w0, w1, w2, w3)
        FMA4(o1, a1, w0, w1, w2, w3)
        FMA4(o2, a2, w0, w1, w2, w3)
        FMA4(o3, a3, w0, w1, w2, w3)
    }
    #pragma unroll
    for (int rr = 0; rr < AD; rr++) {
        float4 m = sM[rr * 16 + ch];
        float x0 = sax[(nl + 0) * 17 + rr], x1 = sax[(nl + 1) * 17 + rr];
        float x2 = sax[(nl + 2) * 17 + rr], x3 = sax[(nl + 3) * 17 + rr];
        o0.x += x0 * m.x; o0.y += x0 * m.y; o0.z += x0 * m.z; o0.w += x0 * m.w;
        o1.x += x1 * m.x; o1.y += x1 * m.y; o1.z += x1 * m.z; o1.w += x1 * m.w;
        o2.x += x2 * m.x; o2.y += x2 * m.y; o2.z += x2 * m.z; o2.w += x2 * m.w;
        o3.x += x3 * m.x; o3.y += x3 * m.y; o3.z += x3 * m.z; o3.w += x3 * m.w;
    }
    ELU4(o0) ELU4(o1) ELU4(o2) ELU4(o3)

    // gp1/gm1 scalars
    {
        float4 p = d_p4[ch], q = d_q4[ch];
        float pp0 = o0.x*p.x + o0.y*p.y + o0.z*p.z + o0.w*p.w;
        float pp1 = o1.x*p.x + o1.y*p.y + o1.z*p.z + o1.w*p.w;
        float pp2 = o2.x*p.x + o2.y*p.y + o2.z*p.z + o2.w*p.w;
        float pp3 = o3.x*p.x + o3.y*p.y + o3.z*p.z + o3.w*p.w;
        float qq0 = o0.x*q.x + o0.y*q.y + o0.z*q.z + o0.w*q.w;
        float qq1 = o1.x*q.x + o1.y*q.y + o1.z*q.z + o1.w*q.w;
        float qq2 = o2.x*q.x + o2.y*q.y + o2.z*q.z + o2.w*q.w;
        float qq3 = o3.x*q.x + o3.y*q.y + o3.z*q.z + o3.w*q.w;
        #pragma unroll
        for (int m = 8; m; m >>= 1) {
            pp0 += __shfl_xor_sync(0xffffffffu, pp0, m, 16);
            pp1 += __shfl_xor_sync(0xffffffffu, pp1, m, 16);
            pp2 += __shfl_xor_sync(0xffffffffu, pp2, m, 16);
            pp3 += __shfl_xor_sync(0xffffffffu, pp3, m, 16);
            qq0 += __shfl_xor_sync(0xffffffffu, qq0, m, 16);
            qq1 += __shfl_xor_sync(0xffffffffu, qq1, m, 16);
            qq2 += __shfl_xor_sync(0xffffffffu, qq2, m, 16);
            qq3 += __shfl_xor_sync(0xffffffffu, qq3, m, 16);
        }
        if (ch == 0) {
            if (nb0 + nl + 0 < NN) { d_gp1[nb0 + nl + 1] = pp0; d_gm1[nb0 + nl + 1] = qq0; }
            if (nb0 + nl + 1 < NN) { d_gp1[nb0 + nl + 2] = pp1; d_gm1[nb0 + nl + 2] = qq1; }
            if (nb0 + nl + 2 < NN) { d_gp1[nb0 + nl + 3] = pp2; d_gm1[nb0 + nl + 3] = qq2; }
            if (nb0 + nl + 3 < NN) { d_gp1[nb0 + nl + 4] = pp3; d_gm1[nb0 + nl + 4] = qq3; }
        }
    }

    // All pass-1 reads of sacc done across the block before overwrite
    __syncthreads();
    *(float4*)&sacc[(nl + 0) * 68 + ch * 4] = o0;
    *(float4*)&sacc[(nl + 1) * 68 + ch * 4] = o1;
    *(float4*)&sacc[(nl + 2) * 68 + ch * 4] = o2;
    *(float4*)&sacc[(nl + 3) * 68 + ch * 4] = o3;
    __syncthreads();

    // ---- pass 2: th1 = hp1 @ Wg (sW still holds Wg) ----
    float4 u0 = make_float4(0.f,0.f,0.f,0.f), u1 = u0, u2 = u0, u3 = u0;
    #pragma unroll
    for (int s4 = 0; s4 < 16; s4++) {
        float4 w0 = sW[(4 * s4 + 0) * 16 + ch];
        float4 w1 = sW[(4 * s4 + 1) * 16 + ch];
        float4 w2 = sW[(4 * s4 + 2) * 16 + ch];
        float4 w3 = sW[(4 * s4 + 3) * 16 + ch];
        float4 a0 = *(float4*)&sacc[(nl + 0) * 68 + s4 * 4];
        float4 a1 = *(float4*)&sacc[(nl + 1) * 68 + s4 * 4];
        float4 a2 = *(float4*)&sacc[(nl + 2) * 68 + s4 * 4];
        float4 a3 = *(float4*)&sacc[(nl + 3) * 68 + s4 * 4];
        FMA4(u0, a0, w0, w1, w2, w3)
        FMA4(u1, a1, w0, w1, w2, w3)
        FMA4(u2, a2, w0, w1, w2, w3)
        FMA4(u3, a3, w0, w1, w2, w3)
    }
    if (nb0 + nl + 0 < NN) d_th1v[(nb0 + nl + 1) * 16 + ch] = u0;
    if (nb0 + nl + 1 < NN) d_th1v[(nb0 + nl + 2) * 16 + ch] = u1;
    if (nb0 + nl + 2 < NN) d_th1v[(nb0 + nl + 3) * 16 + ch] = u2;
    if (nb0 + nl + 3 < NN) d_th1v[(nb0 + nl + 4) * 16 + ch] = u3;
    __syncthreads();

    // ---- pass 3: tm1 = hp1 @ Wm ----
    for (int i = t; i < HH * 16; i += 256) sW[i] = ((const float4*)Wm)[i];
    __syncthreads();
    u0 = make_float4(0.f,0.f,0.f,0.f); u1 = u0; u2 = u0; u3 = u0;
    #pragma unroll
    for (int s4 = 0; s4 < 16; s4++) {
        float4 w0 = sW[(4 * s4 + 0) * 16 + ch];
        float4 w1 = sW[(4 * s4 + 1) * 16 + ch];
        float4 w2 = sW[(4 * s4 + 2) * 16 + ch];
        float4 w3 = sW[(4 * s4 + 3) * 16 + ch];
        float4 a0 = *(float4*)&sacc[(nl + 0) * 68 + s4 * 4];
        float4 a1 = *(float4*)&sacc[(nl + 1) * 68 + s4 * 4];
        float4 a2 = *(float4*)&sacc[(nl + 2) * 68 + s4 * 4];
        float4 a3 = *(float4*)&sacc[(nl + 3) * 68 + s4 * 4];
        FMA4(u0, a0, w0, w1, w2, w3)
        FMA4(u1, a1, w0, w1, w2, w3)
        FMA4(u2, a2, w0, w1, w2, w3)
        FMA4(u3, a3, w0, w1, w2, w3)
    }
    if (nb0 + nl + 0 < NN) d_tm1v[(nb0 + nl + 1) * 16 + ch] = u0;
    if (nb0 + nl + 1 < NN) d_tm1v[(nb0 + nl + 2) * 16 + ch] = u1;
    if (nb0 + nl + 2 < NN) d_tm1v[(nb0 + nl + 3) * 16 + ch] = u2;
    if (nb0 + nl + 3 < NN) d_tm1v[(nb0 + nl + 4) * 16 + ch] = u3;

    if (blockIdx.x == 0 && t < 16) {
        d_th1v[t] = make_float4(0.f, 0.f, 0.f, 0.f);
        d_tm1v[t] = make_float4(0.f, 0.f, 0.f, 0.f);
    }
    if (blockIdx.x == 0 && t == 0) { d_gp1[0] = 0.f; d_gm1[0] = 0.f; }
}

// ---------------- fused alpha + gather + ELU, iteration 2 (final) ----------------
__global__ __launch_bounds__(256) void k_gather2(const int* __restrict__ se,
                                                 const int* __restrict__ bs,
                                                 const int* __restrict__ su,
                                                 const int* __restrict__ sul) {
    __shared__ float4 sbc[8][2][17];
    int t = threadIdx.x, w = t >> 5, l = t & 31, sub = l & 15, half = l >> 4;
    int n = (blockIdx.x * 8 + w) * 2 + half;

    int idx = se[n * KK + sub];
    int e   = bs[n * KK + sub];
    int j   = __ldg(&su[e]);
    float msk = (__ldg(&sul[e]) > 0) ? 1.f : 0.f;
    float v = __ldg(&d_gp1[idx]) + msk * __ldg(&d_gm1[j]);
    v = (v > 0.f) ? v : 0.2f * v;
    float alpha = softmax16((idx == 0) ? NEGINF : v);

    sbc[w][half][sub] = make_float4(alpha, __int_as_float(idx), __int_as_float(j),
                                    alpha * msk);
    __syncwarp();

    float4 acc = make_float4(0.f, 0.f, 0.f, 0.f);
    #pragma unroll
    for (int k = 0; k < KK; k++) {
        float4 b = sbc[w][half][k];
        int i  = __float_as_int(b.y);
        int jj = __float_as_int(b.z);
        float4 vv = d_th1v[i * 16 + sub];
        acc.x += b.x * vv.x; acc.y += b.x * vv.y; acc.z += b.x * vv.z; acc.w += b.x * vv.w;
        float4 u = d_tm1v[jj * 16 + sub];
        acc.x += b.w * u.x; acc.y += b.w * u.y; acc.z += b.w * u.z; acc.w += b.w * u.w;
    }
    ELU4(acc)
    d_hp2v[(n + 1) * 16 + sub] = acc;
    if (blockIdx.x == 0 && t < 16) d_hp2v[t] = make_float4(0.f, 0.f, 0.f, 0.f);
}

// ---------------- readout ----------------------------------------------------------
__global__ __launch_bounds__(256) void k_out(const int* __restrict__ ls,
                                             float* __restrict__ out) {
    int wid = (blockIdx.x * blockDim.x + threadIdx.x) >> 5;
    int l = threadIdx.x & 31;
    int sub = l & 15;
    int mol = wid * 2 + (l >> 4);
    if (mol >= BBATCH) return;
    const int* row = ls + mol * MAXM;
    float4 acc = make_float4(0.f, 0.f, 0.f, 0.f);
    #pragma unroll 8
    for (int m = 0; m < MAXM; m++) {
        int i = __ldg(row + m);
        float4 v = d_hp2v[i * 16 + sub];
        acc.x += v.x; acc.y += v.y; acc.z += v.z; acc.w += v.w;
    }
    ((float4*)out)[mol * 16 + sub] = acc;
}

// ---------------- launch -----------------------------------------------------------
extern "C" void kernel_launch(void* const* d_in, const int* in_sizes, int n_in,
                              void* d_out, int out_size) {
    const float* tf  = (const float*)d_in[0];
    const float* fdg = (const float*)d_in[1];
    const float* rij = (const float*)d_in[2];
    const int*   se  = (const int*)d_in[3];
    const int*   bs  = (const int*)d_in[4];
    const int*   ls  = (const int*)d_in[5];
    const int*   su  = (const int*)d_in[6];
    const int*   sul = (const int*)d_in[7];
    const float* We  = (const float*)d_in[8];
    const float* be  = (const float*)d_in[9];
    const float* Wd  = (const float*)d_in[10];
    const float* bd  = (const float*)d_in[11];
    const float* Wg  = (const float*)d_in[12];
    const float* Wm  = (const float*)d_in[13];
    const float* ag  = (const float*)d_in[14];

    int gat_blocks = NN / 16;               // 3125
    int gemm_blocks = (NN + 63) / 64;       // 782

    k_consts<<<1, 256>>>(Wg, Wm, ag, Wd, bd, We, be);
    k_pre<<<NB_EMB + NB_ELOG, 256>>>(tf, We, be, fdg, rij);

    k_gather1<<<gat_blocks, 256>>>(se, bs, fdg, rij);
    k_mega<<<gemm_blocks, 256>>>(Wg, Wm);
    k_gather2<<<gat_blocks, 256>>>(se, bs, su, sul);

    k_out<<<(BBATCH / 2 + 7) / 8, 256>>>(ls, (float*)d_out);
}